// round 7
// baseline (speedup 1.0000x reference)
#include <cuda_runtime.h>
#include <cuda_bf16.h>
#include <cstdint>
#include <math.h>

#define NN 100000
#define NE 1600000
#define FD 128
#define NG 128
#define GF 32

// ---------------- scratch (device globals; no allocations allowed) ----------
__device__ __align__(16) __nv_bfloat16 g_Uh[(size_t)NN * 256];  // [X|AGG] hi
__device__ __align__(16) __nv_bfloat16 g_Ul[(size_t)NN * 256];  // [X|AGG] lo
__device__ __align__(16) __nv_bfloat16 g_Bh[2 * 128 * 256];     // W^T hi
__device__ __align__(16) __nv_bfloat16 g_Bl[2 * 128 * 256];     // W^T lo
__device__ __align__(16) float g_h0[(size_t)NN * FD];
__device__ int   g_deg[NN];
__device__ int   g_rowptr[NN + 1];
__device__ int   g_fill[NN];
__device__ int   g_col[NE];
__device__ float g_psum[NG * FD];
__device__ float g_pmax[NG * FD];
__device__ int   g_pcnt[NG];
__device__ int   g_bsum[128];

// ---------------- small helpers ---------------------------------------------
__device__ __forceinline__ void atomicMaxF(float* addr, float v) {
    if (v >= 0.f) atomicMax((int*)addr, __float_as_int(v));
    else          atomicMin((unsigned int*)addr, __float_as_uint(v));
}

__device__ __forceinline__ void bsplit(float v, unsigned short& hi, unsigned short& lo) {
    __nv_bfloat16 h = __float2bfloat16(v);
    float r = v - __bfloat162float(h);
    __nv_bfloat16 l = __float2bfloat16(r);
    hi = __bfloat16_as_ushort(h);
    lo = __bfloat16_as_ushort(l);
}

__device__ __forceinline__ uint32_t smem_u32(const void* p) {
    uint32_t a;
    asm("{ .reg .u64 t; cvta.to.shared.u64 t, %1; cvt.u32.u64 %0, t; }"
        : "=r"(a) : "l"(p));
    return a;
}

__device__ __forceinline__ void ldsm4(uint32_t* r, uint32_t addr) {
    asm volatile("ldmatrix.sync.aligned.m8n8.x4.shared.b16 {%0,%1,%2,%3}, [%4];"
                 : "=r"(r[0]), "=r"(r[1]), "=r"(r[2]), "=r"(r[3]) : "r"(addr));
}
__device__ __forceinline__ void ldsm2(uint32_t* r, uint32_t addr) {
    asm volatile("ldmatrix.sync.aligned.m8n8.x2.shared.b16 {%0,%1}, [%2];"
                 : "=r"(r[0]), "=r"(r[1]) : "r"(addr));
}
__device__ __forceinline__ void mma_bf16(float* c, const uint32_t* a, const uint32_t* b) {
    asm volatile(
        "mma.sync.aligned.m16n8k16.row.col.f32.bf16.bf16.f32 "
        "{%0,%1,%2,%3}, {%4,%5,%6,%7}, {%8,%9}, {%0,%1,%2,%3};"
        : "+f"(c[0]), "+f"(c[1]), "+f"(c[2]), "+f"(c[3])
        : "r"(a[0]), "r"(a[1]), "r"(a[2]), "r"(a[3]), "r"(b[0]), "r"(b[1]));
}

// ---------------- CSR build -------------------------------------------------
__global__ void k_init() {
    int i = blockIdx.x * blockDim.x + threadIdx.x;
    if (i < NN) { g_deg[i] = 0; g_fill[i] = 0; }
    if (i < NG * FD) { g_psum[i] = 0.f; g_pmax[i] = -INFINITY; }
}

__global__ void k_hist(const int* __restrict__ edges) {
    int e = blockIdx.x * blockDim.x + threadIdx.x;
    if (e < NE) atomicAdd(&g_deg[edges[NE + e]], 1);
}

#define SCAN_B 1024
__global__ void k_scanA() {
    __shared__ int sm[SCAN_B];
    int i = blockIdx.x * SCAN_B + threadIdx.x;
    int v = (i < NN) ? g_deg[i] : 0;
    sm[threadIdx.x] = v;
    __syncthreads();
    for (int off = 1; off < SCAN_B; off <<= 1) {
        int t = (threadIdx.x >= off) ? sm[threadIdx.x - off] : 0;
        __syncthreads();
        sm[threadIdx.x] += t;
        __syncthreads();
    }
    if (i < NN) g_rowptr[i] = sm[threadIdx.x] - v;   // exclusive
    if (threadIdx.x == SCAN_B - 1) g_bsum[blockIdx.x] = sm[SCAN_B - 1];
}

__global__ void k_scanB(int nb) {                    // parallel Kogge-Stone
    __shared__ int s[128];
    int t = threadIdx.x;
    int v = (t < nb) ? g_bsum[t] : 0;
    s[t] = v;
    __syncthreads();
    for (int off = 1; off < 128; off <<= 1) {
        int u = (t >= off) ? s[t - off] : 0;
        __syncthreads();
        s[t] += u;
        __syncthreads();
    }
    if (t < nb) g_bsum[t] = s[t] - v;                // exclusive
}

__global__ void k_scanC() {
    int i = blockIdx.x * SCAN_B + threadIdx.x;
    if (i < NN) g_rowptr[i] += g_bsum[blockIdx.x];
    if (i == 0) g_rowptr[NN] = NE;
}

__global__ void k_fillcol(const int* __restrict__ edges) {
    int e = blockIdx.x * blockDim.x + threadIdx.x;
    if (e < NE) {
        int t = edges[NE + e];
        int p = g_rowptr[t] + atomicAdd(&g_fill[t], 1);
        g_col[p] = edges[e];
    }
}

// ---------------- per-graph node counts (sorted batch_idx) ------------------
__global__ void k_cnt(const int* __restrict__ batch) {
    int g = threadIdx.x;                             // 128 threads
    int lo = 0, hi = NN;
    while (lo < hi) { int mid = (lo + hi) >> 1; if (batch[mid] < g) lo = mid + 1; else hi = mid; }
    int lb = lo;
    lo = 0; hi = NN;
    while (lo < hi) { int mid = (lo + hi) >> 1; if (batch[mid] <= g) lo = mid + 1; else hi = mid; }
    g_pcnt[g] = lo - lb;
}

// ---------------- weight prep: V = [Wr;Wl] -> Bt[n][k] hi/lo bf16 -----------
__global__ void k_prepw(const float* __restrict__ Wr0, const float* __restrict__ Wl0,
                        const float* __restrict__ Wr1, const float* __restrict__ Wl1) {
    int idx = blockIdx.x * 256 + threadIdx.x;        // 65536 total
    int L = idx >> 15;
    int rem = idx & 32767;
    int k = rem >> 7, n = rem & 127;
    const float* Wr = L ? Wr1 : Wr0;
    const float* Wl = L ? Wl1 : Wl0;
    float v = (k < FD) ? Wr[k * FD + n] : Wl[(k - FD) * FD + n];
    unsigned short hi, lo;
    bsplit(v, hi, lo);
    g_Bh[L * 32768 + n * 256 + k] = __ushort_as_bfloat16(hi);
    g_Bl[L * 32768 + n * 256 + k] = __ushort_as_bfloat16(lo);
}

// ---------------- split X into bf16 hi/lo (cols 0..127 of U) ----------------
__global__ void k_split_x(const float* __restrict__ X) {
    int i = blockIdx.x * 256 + threadIdx.x;          // over NN*32 float4
    if (i >= NN * 32) return;
    float4 v = ((const float4*)X)[i];
    int node = i >> 5, q = (i & 31) * 4;
    union { unsigned short s[4]; uint2 u; } ph, pl;
    bsplit(v.x, ph.s[0], pl.s[0]);
    bsplit(v.y, ph.s[1], pl.s[1]);
    bsplit(v.z, ph.s[2], pl.s[2]);
    bsplit(v.w, ph.s[3], pl.s[3]);
    *(uint2*)(g_Uh + (size_t)node * 256 + q) = ph.u;
    *(uint2*)(g_Ul + (size_t)node * 256 + q) = pl.u;
}

// ---------------- neighbor mean aggregation -> bf16 hi/lo (cols 128..255) ---
__global__ void k_aggregate(const float* __restrict__ X) {
    int node = blockIdx.x * 8 + (threadIdx.x >> 5);
    int lane = threadIdx.x & 31;
    if (node >= NN) return;
    int beg = g_rowptr[node], end = g_rowptr[node + 1];
    const float4* Xv = (const float4*)X;
    float4 s = make_float4(0.f, 0.f, 0.f, 0.f);
    int e = beg;
    for (; e + 3 < end; e += 4) {
        int i0 = g_col[e], i1 = g_col[e + 1], i2 = g_col[e + 2], i3 = g_col[e + 3];
        float4 a = Xv[(size_t)i0 * 32 + lane];
        float4 b = Xv[(size_t)i1 * 32 + lane];
        float4 c = Xv[(size_t)i2 * 32 + lane];
        float4 d = Xv[(size_t)i3 * 32 + lane];
        s.x += (a.x + b.x) + (c.x + d.x);
        s.y += (a.y + b.y) + (c.y + d.y);
        s.z += (a.z + b.z) + (c.z + d.z);
        s.w += (a.w + b.w) + (c.w + d.w);
    }
    for (; e < end; e++) {
        float4 v = Xv[(size_t)g_col[e] * 32 + lane];
        s.x += v.x; s.y += v.y; s.z += v.z; s.w += v.w;
    }
    float sc = 1.f / fmaxf((float)(end - beg), 1.f);
    union { unsigned short s[4]; uint2 u; } ph, pl;
    bsplit(s.x * sc, ph.s[0], pl.s[0]);
    bsplit(s.y * sc, ph.s[1], pl.s[1]);
    bsplit(s.z * sc, ph.s[2], pl.s[2]);
    bsplit(s.w * sc, ph.s[3], pl.s[3]);
    size_t off = (size_t)node * 256 + 128 + lane * 4;
    *(uint2*)(g_Uh + off) = ph.u;
    *(uint2*)(g_Ul + off) = pl.u;
}

// ---------------- mma.sync GEMM (R4 structure, 2 CTA/SM) --------------------
// CTA: 128 nodes x 128 outs; 8 warps 2(M)x4(N); warp tile 64x32; K=256 by 64.
#define TP 72
#define TILE_B (128 * TP * 2)                 // 18432 bytes per tile
#define POOL_SEGS 16
#define GEMM_SMEM (4 * TILE_B + 512 + 512)

__device__ __forceinline__ void load_chunk(__nv_bfloat16* dst,
                                           const __nv_bfloat16* __restrict__ src,
                                           int row0, int rowmax, int kofs) {
    for (int i = threadIdx.x; i < 1024; i += 256) {  // uint4 units (8 bf16)
        int r = i >> 3, q = i & 7;
        int gr = row0 + r;
        uint4 v = make_uint4(0, 0, 0, 0);
        if (gr < rowmax) v = *(const uint4*)(src + (size_t)gr * 256 + kofs + q * 8);
        *(uint4*)(dst + r * TP + q * 8) = v;
    }
}

__global__ __launch_bounds__(256, 2) void k_gemm(
    const __nv_bfloat16* __restrict__ Uh, const __nv_bfloat16* __restrict__ Ul,
    const __nv_bfloat16* __restrict__ Bh, const __nv_bfloat16* __restrict__ Bl,
    const float* __restrict__ bias, float* __restrict__ OUT,
    __nv_bfloat16* __restrict__ NUh, __nv_bfloat16* __restrict__ NUl,
    const int* __restrict__ batch, int relu, int wsplit, int pool)
{
    extern __shared__ char smem[];
    __nv_bfloat16* sUh = (__nv_bfloat16*)smem;
    __nv_bfloat16* sUl = (__nv_bfloat16*)(smem + TILE_B);
    __nv_bfloat16* sBh = (__nv_bfloat16*)(smem + 2 * TILE_B);
    __nv_bfloat16* sBl = (__nv_bfloat16*)(smem + 3 * TILE_B);
    float* sbias  = (float*)(smem + 4 * TILE_B);
    int*   sbatch = (int*)(smem + 4 * TILE_B + 512);

    const int tid = threadIdx.x, wid = tid >> 5, lid = tid & 31;
    const int wm = wid >> 2, wn = wid & 3;
    const int node0 = blockIdx.x * 128;

    if (tid < FD) {
        sbias[tid] = bias[tid];
        if (pool) {
            int n = node0 + tid;
            sbatch[tid] = (n < NN) ? batch[n] : 0;
        }
    }

    float acc[4][4][4];
#pragma unroll
    for (int mt = 0; mt < 4; mt++)
#pragma unroll
        for (int nt = 0; nt < 4; nt++)
#pragma unroll
            for (int j = 0; j < 4; j++) acc[mt][nt][j] = 0.f;

    uint32_t aUh = smem_u32(sUh), aUl = smem_u32(sUl);
    uint32_t aBh = smem_u32(sBh), aBl = smem_u32(sBl);
    const uint32_t a_lane = (uint32_t)((lid & 15) * (TP * 2) + ((lid >> 4) << 4));
    const uint32_t b_lane = (uint32_t)((lid & 7) * (TP * 2) + (((lid >> 3) & 1) << 4));

    for (int c = 0; c < 4; c++) {
        load_chunk(sUh, Uh, node0, NN, c * 64);
        load_chunk(sUl, Ul, node0, NN, c * 64);
        load_chunk(sBh, Bh, 0, 128, c * 64);
        load_chunk(sBl, Bl, 0, 128, c * 64);
        __syncthreads();
#pragma unroll
        for (int ks = 0; ks < 4; ks++) {
            uint32_t ah[4][4], al[4][4];
#pragma unroll
            for (int mt = 0; mt < 4; mt++) {
                uint32_t roff = (uint32_t)((wm * 64 + mt * 16) * (TP * 2) + ks * 32);
                ldsm4(ah[mt], aUh + roff + a_lane);
                ldsm4(al[mt], aUl + roff + a_lane);
            }
#pragma unroll
            for (int nt = 0; nt < 4; nt++) {
                uint32_t bh[2], bl[2];
                uint32_t roff = (uint32_t)((wn * 32 + nt * 8) * (TP * 2) + ks * 32);
                ldsm2(bh, aBh + roff + b_lane);
                ldsm2(bl, aBl + roff + b_lane);
#pragma unroll
                for (int mt = 0; mt < 4; mt++) {
                    mma_bf16(acc[mt][nt], ah[mt], bh);
                    mma_bf16(acc[mt][nt], al[mt], bh);
                    mma_bf16(acc[mt][nt], ah[mt], bl);
                }
            }
        }
        __syncthreads();
    }

    const int tq = lid >> 2, tr = lid & 3;

    if (!pool) {
        // epilogue: bias (+relu), store fp32 rows (+ bf16 hi/lo split)
#pragma unroll
        for (int mt = 0; mt < 4; mt++) {
#pragma unroll
            for (int h = 0; h < 2; h++) {
                int node = node0 + wm * 64 + mt * 16 + tq + h * 8;
                if (node >= NN) continue;
#pragma unroll
                for (int nt = 0; nt < 4; nt++) {
                    int col = wn * 32 + nt * 8 + tr * 2;
                    float v0 = acc[mt][nt][h * 2 + 0] + sbias[col];
                    float v1 = acc[mt][nt][h * 2 + 1] + sbias[col + 1];
                    if (relu) { v0 = fmaxf(v0, 0.f); v1 = fmaxf(v1, 0.f); }
                    *(float2*)(OUT + (size_t)node * FD + col) = make_float2(v0, v1);
                    if (wsplit) {
                        union { unsigned short s[2]; uint32_t u; } ph, pl;
                        bsplit(v0, ph.s[0], pl.s[0]);
                        bsplit(v1, ph.s[1], pl.s[1]);
                        *(uint32_t*)(NUh + (size_t)node * 256 + col) = ph.u;
                        *(uint32_t*)(NUl + (size_t)node * 256 + col) = pl.u;
                    }
                }
            }
        }
        return;
    }

    // fused pooling epilogue (layer 1): segment sum/max per graph, no OUT write
    float* psumS = (float*)smem;                      // [POOL_SEGS][128]
    float* pmaxS = (float*)smem + POOL_SEGS * 128;    // [POOL_SEGS][128]
    for (int i = tid; i < POOL_SEGS * 128; i += 256) {
        psumS[i] = 0.f;
        pmaxS[i] = -INFINITY;
    }
    __syncthreads();

    int seg0 = sbatch[0];
    int lastn = min(127, NN - 1 - node0);
    int span = sbatch[lastn] - seg0;                  // inclusive span - 1
    bool fast = (span < POOL_SEGS);

    int curseg = -1;
    float aS[8], aM[8];
#pragma unroll
    for (int j = 0; j < 8; j++) { aS[j] = 0.f; aM[j] = -INFINITY; }

    for (int mt = 0; mt < 4; mt++) {
        for (int h = 0; h < 2; h++) {
            int ln = wm * 64 + mt * 16 + tq + h * 8;
            int node = node0 + ln;
            if (node >= NN) continue;
            int seg = sbatch[ln];
            if (seg != curseg) {
                if (curseg >= 0) {
#pragma unroll
                    for (int j = 0; j < 8; j++) {
                        int col = wn * 32 + (j >> 1) * 8 + tr * 2 + (j & 1);
                        if (fast) {
                            atomicAdd(&psumS[(curseg - seg0) * 128 + col], aS[j]);
                            atomicMaxF(&pmaxS[(curseg - seg0) * 128 + col], aM[j]);
                        } else {
                            atomicAdd(&g_psum[curseg * 128 + col], aS[j]);
                            atomicMaxF(&g_pmax[curseg * 128 + col], aM[j]);
                        }
                        aS[j] = 0.f; aM[j] = -INFINITY;
                    }
                }
                curseg = seg;
            }
#pragma unroll
            for (int nt = 0; nt < 4; nt++) {
#pragma unroll
                for (int cc = 0; cc < 2; cc++) {
                    int col = wn * 32 + nt * 8 + tr * 2 + cc;
                    float v = acc[mt][nt][h * 2 + cc] + sbias[col];
                    int j = nt * 2 + cc;
                    aS[j] += v;
                    aM[j] = fmaxf(aM[j], v);
                }
            }
        }
    }
    if (curseg >= 0) {
#pragma unroll
        for (int j = 0; j < 8; j++) {
            int col = wn * 32 + (j >> 1) * 8 + tr * 2 + (j & 1);
            if (fast) {
                atomicAdd(&psumS[(curseg - seg0) * 128 + col], aS[j]);
                atomicMaxF(&pmaxS[(curseg - seg0) * 128 + col], aM[j]);
            } else {
                atomicAdd(&g_psum[curseg * 128 + col], aS[j]);
                atomicMaxF(&g_pmax[curseg * 128 + col], aM[j]);
            }
        }
    }
    __syncthreads();
    if (fast) {
        for (int i = tid; i < (span + 1) * 128; i += 256) {
            int s = i >> 7, col = i & 127;
            atomicAdd(&g_psum[(seg0 + s) * 128 + col], psumS[s * 128 + col]);
            atomicMaxF(&g_pmax[(seg0 + s) * 128 + col], pmaxS[s * 128 + col]);
        }
    }
}

// ---------------- readout head ---------------------------------------------
__global__ void k_readout(const float* __restrict__ gfeat,
                          const float* __restrict__ Wg, const float* __restrict__ bg,
                          const float* __restrict__ Wo, const float* __restrict__ bo,
                          float* __restrict__ out) {
    __shared__ float flat[3 * FD];
    __shared__ float logits[2];
    int g = blockIdx.x, o = threadIdx.x;     // 128 threads
    float cnt = fmaxf((float)g_pcnt[g], 1.f);
    flat[o]       = g_psum[g * FD + o] / cnt;
    flat[FD + o]  = g_pmax[g * FD + o];
    float acc = bg[o];
#pragma unroll
    for (int k = 0; k < GF; k++) acc += gfeat[g * GF + k] * Wg[k * FD + o];
    flat[2 * FD + o] = acc;
    __syncthreads();
    if (o < 2) {
        float l = bo[o];
        for (int j = 0; j < 3 * FD; j++) l += flat[j] * Wo[j * 2 + o];
        logits[o] = l;
    }
    __syncthreads();
    if (o < 2) {
        float mm  = fmaxf(logits[0], logits[1]);
        float lse = mm + logf(expf(logits[0] - mm) + expf(logits[1] - mm));
        out[g * 2 + o] = logits[o] - lse;
    }
}

// ---------------- launch -----------------------------------------------------
extern "C" void kernel_launch(void* const* d_in, const int* in_sizes, int n_in,
                              void* d_out, int out_size) {
    const float* x     = (const float*)d_in[0];
    const int*   edges = (const int*)  d_in[1];
    const int*   batch = (const int*)  d_in[2];
    const float* gfeat = (const float*)d_in[3];
    const float* Wl0   = (const float*)d_in[4];
    const float* bl0   = (const float*)d_in[5];
    const float* Wr0   = (const float*)d_in[6];
    const float* Wl1   = (const float*)d_in[7];
    const float* bl1   = (const float*)d_in[8];
    const float* Wr1   = (const float*)d_in[9];
    const float* Wg    = (const float*)d_in[10];
    const float* bg    = (const float*)d_in[11];
    const float* Wo    = (const float*)d_in[12];
    const float* bo    = (const float*)d_in[13];
    float* out = (float*)d_out;

    cudaFuncSetAttribute(k_gemm, cudaFuncAttributeMaxDynamicSharedMemorySize,
                         GEMM_SMEM);

    __nv_bfloat16 *pUh, *pUl, *pBh, *pBl;
    float *p_h0;
    cudaGetSymbolAddress((void**)&pUh, g_Uh);
    cudaGetSymbolAddress((void**)&pUl, g_Ul);
    cudaGetSymbolAddress((void**)&pBh, g_Bh);
    cudaGetSymbolAddress((void**)&pBl, g_Bl);
    cudaGetSymbolAddress((void**)&p_h0, g_h0);

    const int scan_nb = (NN + SCAN_B - 1) / SCAN_B;   // 98
    const int gemm_nb = (NN + 127) / 128;             // 782

    k_init<<<(NN + 255) / 256, 256>>>();
    k_hist<<<(NE + 255) / 256, 256>>>(edges);
    k_scanA<<<scan_nb, SCAN_B>>>();
    k_scanB<<<1, 128>>>(scan_nb);
    k_scanC<<<scan_nb, SCAN_B>>>();
    k_fillcol<<<(NE + 255) / 256, 256>>>(edges);

    k_prepw<<<256, 256>>>(Wr0, Wl0, Wr1, Wl1);
    k_cnt<<<1, 128>>>(batch);
    k_split_x<<<(NN * 32 + 255) / 256, 256>>>(x);

    // layer 0: writes h0 (fp32) and its bf16 split into U cols 0..127
    k_aggregate<<<(NN + 7) / 8, 256>>>(x);
    k_gemm<<<gemm_nb, 256, GEMM_SMEM>>>(pUh, pUl, pBh, pBl, bl0, p_h0,
                                        pUh, pUl, nullptr, 1, 1, 0);
    // layer 1: pooling fused into epilogue (no h1 materialization)
    k_aggregate<<<(NN + 7) / 8, 256>>>(p_h0);
    k_gemm<<<gemm_nb, 256, GEMM_SMEM>>>(pUh, pUl, pBh + 32768, pBl + 32768, bl1,
                                        nullptr, nullptr, nullptr, batch, 0, 0, 1);

    k_readout<<<NG, FD>>>(gfeat, Wg, bg, Wo, bo, out);
}

// round 8
// speedup vs baseline: 1.3426x; 1.3426x over previous
#include <cuda_runtime.h>
#include <cuda_bf16.h>
#include <cuda_fp16.h>
#include <cstdint>
#include <math.h>

#define NN 100000
#define NE 1600000
#define FD 128
#define NG 128
#define GF 32

// ---------------- scratch (device globals; no allocations allowed) ----------
__device__ __align__(16) __nv_bfloat16 g_Uh[(size_t)NN * 256];  // [X|AGG] hi
__device__ __align__(16) __nv_bfloat16 g_Ul[(size_t)NN * 256];  // [X|AGG] lo
__device__ __align__(16) __nv_bfloat16 g_Bh[2 * 128 * 256];     // W^T hi
__device__ __align__(16) __nv_bfloat16 g_Bl[2 * 128 * 256];     // W^T lo
__device__ __align__(16) __half g_Xh[(size_t)NN * FD];          // fp16 mirror of x
__device__ __align__(16) __half g_Hh[(size_t)NN * FD];          // fp16 mirror of h0
__device__ __align__(16) float g_h0[(size_t)NN * FD];
__device__ __align__(16) float g_h1[(size_t)NN * FD];
__device__ int   g_deg[NN];
__device__ int   g_rowptr[NN + 1];
__device__ int   g_fill[NN];
__device__ int   g_col[NE];
__device__ float g_psum[NG * FD];
__device__ float g_pmax[NG * FD];
__device__ int   g_pcnt[NG];
__device__ int   g_bsum[128];

// ---------------- small helpers ---------------------------------------------
__device__ __forceinline__ void atomicMaxF(float* addr, float v) {
    if (v >= 0.f) atomicMax((int*)addr, __float_as_int(v));
    else          atomicMin((unsigned int*)addr, __float_as_uint(v));
}

__device__ __forceinline__ void bsplit(float v, unsigned short& hi, unsigned short& lo) {
    __nv_bfloat16 h = __float2bfloat16(v);
    float r = v - __bfloat162float(h);
    __nv_bfloat16 l = __float2bfloat16(r);
    hi = __bfloat16_as_ushort(h);
    lo = __bfloat16_as_ushort(l);
}

__device__ __forceinline__ uint32_t smem_u32(const void* p) {
    uint32_t a;
    asm("{ .reg .u64 t; cvta.to.shared.u64 t, %1; cvt.u32.u64 %0, t; }"
        : "=r"(a) : "l"(p));
    return a;
}

__device__ __forceinline__ void ldsm4(uint32_t* r, uint32_t addr) {
    asm volatile("ldmatrix.sync.aligned.m8n8.x4.shared.b16 {%0,%1,%2,%3}, [%4];"
                 : "=r"(r[0]), "=r"(r[1]), "=r"(r[2]), "=r"(r[3]) : "r"(addr));
}
__device__ __forceinline__ void ldsm2(uint32_t* r, uint32_t addr) {
    asm volatile("ldmatrix.sync.aligned.m8n8.x2.shared.b16 {%0,%1}, [%2];"
                 : "=r"(r[0]), "=r"(r[1]) : "r"(addr));
}
__device__ __forceinline__ void mma_bf16(float* c, const uint32_t* a, const uint32_t* b) {
    asm volatile(
        "mma.sync.aligned.m16n8k16.row.col.f32.bf16.bf16.f32 "
        "{%0,%1,%2,%3}, {%4,%5,%6,%7}, {%8,%9}, {%0,%1,%2,%3};"
        : "+f"(c[0]), "+f"(c[1]), "+f"(c[2]), "+f"(c[3])
        : "r"(a[0]), "r"(a[1]), "r"(a[2]), "r"(a[3]), "r"(b[0]), "r"(b[1]));
}

// ---------------- CSR build -------------------------------------------------
__global__ void k_init() {
    int i = blockIdx.x * blockDim.x + threadIdx.x;
    if (i < NN) { g_deg[i] = 0; g_fill[i] = 0; }
    if (i < NG * FD) { g_psum[i] = 0.f; g_pmax[i] = -INFINITY; }
    if (i < NG) g_pcnt[i] = 0;
}

__global__ void k_hist(const int* __restrict__ edges) {
    int e = blockIdx.x * blockDim.x + threadIdx.x;
    if (e < NE) atomicAdd(&g_deg[edges[NE + e]], 1);
}

#define SCAN_B 1024
__global__ void k_scanA() {
    __shared__ int sm[SCAN_B];
    int i = blockIdx.x * SCAN_B + threadIdx.x;
    int v = (i < NN) ? g_deg[i] : 0;
    sm[threadIdx.x] = v;
    __syncthreads();
    for (int off = 1; off < SCAN_B; off <<= 1) {
        int t = (threadIdx.x >= off) ? sm[threadIdx.x - off] : 0;
        __syncthreads();
        sm[threadIdx.x] += t;
        __syncthreads();
    }
    if (i < NN) g_rowptr[i] = sm[threadIdx.x] - v;   // exclusive
    if (threadIdx.x == SCAN_B - 1) g_bsum[blockIdx.x] = sm[SCAN_B - 1];
}

__global__ void k_scanB(int nb) {                    // parallel Kogge-Stone
    __shared__ int s[128];
    int t = threadIdx.x;
    int v = (t < nb) ? g_bsum[t] : 0;
    s[t] = v;
    __syncthreads();
    for (int off = 1; off < 128; off <<= 1) {
        int u = (t >= off) ? s[t - off] : 0;
        __syncthreads();
        s[t] += u;
        __syncthreads();
    }
    if (t < nb) g_bsum[t] = s[t] - v;                // exclusive
}

__global__ void k_scanC() {
    int i = blockIdx.x * SCAN_B + threadIdx.x;
    if (i < NN) g_rowptr[i] += g_bsum[blockIdx.x];
    if (i == 0) g_rowptr[NN] = NE;
}

__global__ void k_fillcol(const int* __restrict__ edges) {
    int e = blockIdx.x * blockDim.x + threadIdx.x;
    if (e < NE) {
        int t = edges[NE + e];
        int p = g_rowptr[t] + atomicAdd(&g_fill[t], 1);
        g_col[p] = edges[e];
    }
}

// ---------------- weight prep: V = [Wr;Wl] -> Bt[n][k] hi/lo bf16 -----------
__global__ void k_prepw(const float* __restrict__ Wr0, const float* __restrict__ Wl0,
                        const float* __restrict__ Wr1, const float* __restrict__ Wl1) {
    int idx = blockIdx.x * 256 + threadIdx.x;        // 65536 total
    int L = idx >> 15;
    int rem = idx & 32767;
    int k = rem >> 7, n = rem & 127;
    const float* Wr = L ? Wr1 : Wr0;
    const float* Wl = L ? Wl1 : Wl0;
    float v = (k < FD) ? Wr[k * FD + n] : Wl[(k - FD) * FD + n];
    unsigned short hi, lo;
    bsplit(v, hi, lo);
    g_Bh[L * 32768 + n * 256 + k] = __ushort_as_bfloat16(hi);
    g_Bl[L * 32768 + n * 256 + k] = __ushort_as_bfloat16(lo);
}

// ---------------- split X: bf16 hi/lo (U cols 0..127) + fp16 mirror ---------
__global__ void k_split_x(const float* __restrict__ X) {
    int i = blockIdx.x * 256 + threadIdx.x;          // over NN*32 float4
    if (i >= NN * 32) return;
    float4 v = ((const float4*)X)[i];
    int node = i >> 5, q = (i & 31) * 4;
    union { unsigned short s[4]; uint2 u; } ph, pl;
    bsplit(v.x, ph.s[0], pl.s[0]);
    bsplit(v.y, ph.s[1], pl.s[1]);
    bsplit(v.z, ph.s[2], pl.s[2]);
    bsplit(v.w, ph.s[3], pl.s[3]);
    *(uint2*)(g_Uh + (size_t)node * 256 + q) = ph.u;
    *(uint2*)(g_Ul + (size_t)node * 256 + q) = pl.u;
    union { __half2 h2[2]; uint2 u; } hh;
    hh.h2[0] = __floats2half2_rn(v.x, v.y);
    hh.h2[1] = __floats2half2_rn(v.z, v.w);
    *(uint2*)(g_Xh + (size_t)node * FD + q) = hh.u;
}

// ---------------- neighbor mean aggregation (fp16 gather) -------------------
// Gathers fp16 rows (256B each), accumulates fp32, writes bf16 hi/lo to
// U cols 128..255. Halves the L2 gather traffic vs fp32.
__global__ void k_aggregate(const __half* __restrict__ H) {
    int node = blockIdx.x * 8 + (threadIdx.x >> 5);
    int lane = threadIdx.x & 31;
    if (node >= NN) return;
    int beg = g_rowptr[node], end = g_rowptr[node + 1];
    const uint2* Hv = (const uint2*)H;               // 4 halves per lane
    float4 s = make_float4(0.f, 0.f, 0.f, 0.f);
    int e = beg;
    for (; e + 3 < end; e += 4) {
        int i0 = g_col[e], i1 = g_col[e + 1], i2 = g_col[e + 2], i3 = g_col[e + 3];
        uint2 u0 = Hv[(size_t)i0 * 32 + lane];
        uint2 u1 = Hv[(size_t)i1 * 32 + lane];
        uint2 u2 = Hv[(size_t)i2 * 32 + lane];
        uint2 u3 = Hv[(size_t)i3 * 32 + lane];
        float2 a0 = __half22float2(*(__half2*)&u0.x), a1 = __half22float2(*(__half2*)&u0.y);
        float2 b0 = __half22float2(*(__half2*)&u1.x), b1 = __half22float2(*(__half2*)&u1.y);
        float2 c0 = __half22float2(*(__half2*)&u2.x), c1 = __half22float2(*(__half2*)&u2.y);
        float2 d0 = __half22float2(*(__half2*)&u3.x), d1 = __half22float2(*(__half2*)&u3.y);
        s.x += (a0.x + b0.x) + (c0.x + d0.x);
        s.y += (a0.y + b0.y) + (c0.y + d0.y);
        s.z += (a1.x + b1.x) + (c1.x + d1.x);
        s.w += (a1.y + b1.y) + (c1.y + d1.y);
    }
    for (; e < end; e++) {
        uint2 u = Hv[(size_t)g_col[e] * 32 + lane];
        float2 f0 = __half22float2(*(__half2*)&u.x), f1 = __half22float2(*(__half2*)&u.y);
        s.x += f0.x; s.y += f0.y; s.z += f1.x; s.w += f1.y;
    }
    float sc = 1.f / fmaxf((float)(end - beg), 1.f);
    union { unsigned short s[4]; uint2 u; } ph, pl;
    bsplit(s.x * sc, ph.s[0], pl.s[0]);
    bsplit(s.y * sc, ph.s[1], pl.s[1]);
    bsplit(s.z * sc, ph.s[2], pl.s[2]);
    bsplit(s.w * sc, ph.s[3], pl.s[3]);
    size_t off = (size_t)node * 256 + 128 + lane * 4;
    *(uint2*)(g_Uh + off) = ph.u;
    *(uint2*)(g_Ul + off) = pl.u;
}

// ---------------- mma.sync GEMM (R4 structure, 2 CTA/SM) --------------------
// CTA: 128 nodes x 128 outs; 8 warps 2(M)x4(N); warp tile 64x32; K=256 by 64.
#define TP 72
#define TILE_B (128 * TP * 2)                 // 18432 bytes per tile
#define GEMM_SMEM (4 * TILE_B + 512)

__device__ __forceinline__ void load_chunk(__nv_bfloat16* dst,
                                           const __nv_bfloat16* __restrict__ src,
                                           int row0, int rowmax, int kofs) {
    for (int i = threadIdx.x; i < 1024; i += 256) {  // uint4 units (8 bf16)
        int r = i >> 3, q = i & 7;
        int gr = row0 + r;
        uint4 v = make_uint4(0, 0, 0, 0);
        if (gr < rowmax) v = *(const uint4*)(src + (size_t)gr * 256 + kofs + q * 8);
        *(uint4*)(dst + r * TP + q * 8) = v;
    }
}

__global__ __launch_bounds__(256, 2) void k_gemm(
    const __nv_bfloat16* __restrict__ Uh, const __nv_bfloat16* __restrict__ Ul,
    const __nv_bfloat16* __restrict__ Bh, const __nv_bfloat16* __restrict__ Bl,
    const float* __restrict__ bias, float* __restrict__ OUT,
    __nv_bfloat16* __restrict__ NUh, __nv_bfloat16* __restrict__ NUl,
    __half* __restrict__ NH, int relu, int wsplit)
{
    extern __shared__ char smem[];
    __nv_bfloat16* sUh = (__nv_bfloat16*)smem;
    __nv_bfloat16* sUl = (__nv_bfloat16*)(smem + TILE_B);
    __nv_bfloat16* sBh = (__nv_bfloat16*)(smem + 2 * TILE_B);
    __nv_bfloat16* sBl = (__nv_bfloat16*)(smem + 3 * TILE_B);
    float* sbias = (float*)(smem + 4 * TILE_B);

    const int tid = threadIdx.x, wid = tid >> 5, lid = tid & 31;
    const int wm = wid >> 2, wn = wid & 3;
    const int node0 = blockIdx.x * 128;

    if (tid < FD) sbias[tid] = bias[tid];

    float acc[4][4][4];
#pragma unroll
    for (int mt = 0; mt < 4; mt++)
#pragma unroll
        for (int nt = 0; nt < 4; nt++)
#pragma unroll
            for (int j = 0; j < 4; j++) acc[mt][nt][j] = 0.f;

    uint32_t aUh = smem_u32(sUh), aUl = smem_u32(sUl);
    uint32_t aBh = smem_u32(sBh), aBl = smem_u32(sBl);
    const uint32_t a_lane = (uint32_t)((lid & 15) * (TP * 2) + ((lid >> 4) << 4));
    const uint32_t b_lane = (uint32_t)((lid & 7) * (TP * 2) + (((lid >> 3) & 1) << 4));

    for (int c = 0; c < 4; c++) {
        load_chunk(sUh, Uh, node0, NN, c * 64);
        load_chunk(sUl, Ul, node0, NN, c * 64);
        load_chunk(sBh, Bh, 0, 128, c * 64);
        load_chunk(sBl, Bl, 0, 128, c * 64);
        __syncthreads();
#pragma unroll
        for (int ks = 0; ks < 4; ks++) {
            uint32_t ah[4][4], al[4][4];
#pragma unroll
            for (int mt = 0; mt < 4; mt++) {
                uint32_t roff = (uint32_t)((wm * 64 + mt * 16) * (TP * 2) + ks * 32);
                ldsm4(ah[mt], aUh + roff + a_lane);
                ldsm4(al[mt], aUl + roff + a_lane);
            }
#pragma unroll
            for (int nt = 0; nt < 4; nt++) {
                uint32_t bh[2], bl[2];
                uint32_t roff = (uint32_t)((wn * 32 + nt * 8) * (TP * 2) + ks * 32);
                ldsm2(bh, aBh + roff + b_lane);
                ldsm2(bl, aBl + roff + b_lane);
#pragma unroll
                for (int mt = 0; mt < 4; mt++) {
                    mma_bf16(acc[mt][nt], ah[mt], bh);
                    mma_bf16(acc[mt][nt], al[mt], bh);
                    mma_bf16(acc[mt][nt], ah[mt], bl);
                }
            }
        }
        __syncthreads();
    }

    // epilogue: c-fragment (row = t/4 [+8], col = 2*(t%4) [+1])
    const int tq = lid >> 2, tr = lid & 3;
#pragma unroll
    for (int mt = 0; mt < 4; mt++) {
#pragma unroll
        for (int h = 0; h < 2; h++) {
            int node = node0 + wm * 64 + mt * 16 + tq + h * 8;
            if (node >= NN) continue;
#pragma unroll
            for (int nt = 0; nt < 4; nt++) {
                int col = wn * 32 + nt * 8 + tr * 2;
                float v0 = acc[mt][nt][h * 2 + 0] + sbias[col];
                float v1 = acc[mt][nt][h * 2 + 1] + sbias[col + 1];
                if (relu) { v0 = fmaxf(v0, 0.f); v1 = fmaxf(v1, 0.f); }
                *(float2*)(OUT + (size_t)node * FD + col) = make_float2(v0, v1);
                if (wsplit) {
                    union { unsigned short s[2]; uint32_t u; } ph, pl;
                    bsplit(v0, ph.s[0], pl.s[0]);
                    bsplit(v1, ph.s[1], pl.s[1]);
                    *(uint32_t*)(NUh + (size_t)node * 256 + col) = ph.u;
                    *(uint32_t*)(NUl + (size_t)node * 256 + col) = pl.u;
                    __half2 hv = __floats2half2_rn(v0, v1);
                    *(__half2*)(NH + (size_t)node * FD + col) = hv;
                }
            }
        }
    }
}

// ---------------- pooling (sorted batch_idx, warp-local segments) -----------
__global__ void k_pool(const float* __restrict__ H, const int* __restrict__ batch) {
    int wg   = (blockIdx.x * blockDim.x + threadIdx.x) >> 5;
    int lane = threadIdx.x & 31;
    int n0 = wg * 64;
    if (n0 >= NN) return;
    int n1 = min(n0 + 64, NN);
    const float4* Hv = (const float4*)H;
    float4 s = make_float4(0.f, 0.f, 0.f, 0.f);
    float4 m = make_float4(-INFINITY, -INFINITY, -INFINITY, -INFINITY);
    int cnt = 0, cur = batch[n0];
    for (int n = n0; n < n1; n++) {
        int g = batch[n];
        if (g != cur) {
            int base = cur * FD + lane * 4;
            atomicAdd(&g_psum[base + 0], s.x); atomicAdd(&g_psum[base + 1], s.y);
            atomicAdd(&g_psum[base + 2], s.z); atomicAdd(&g_psum[base + 3], s.w);
            atomicMaxF(&g_pmax[base + 0], m.x); atomicMaxF(&g_pmax[base + 1], m.y);
            atomicMaxF(&g_pmax[base + 2], m.z); atomicMaxF(&g_pmax[base + 3], m.w);
            if (lane == 0) atomicAdd(&g_pcnt[cur], cnt);
            s = make_float4(0.f, 0.f, 0.f, 0.f);
            m = make_float4(-INFINITY, -INFINITY, -INFINITY, -INFINITY);
            cnt = 0; cur = g;
        }
        float4 v = Hv[(size_t)n * 32 + lane];
        s.x += v.x; s.y += v.y; s.z += v.z; s.w += v.w;
        m.x = fmaxf(m.x, v.x); m.y = fmaxf(m.y, v.y);
        m.z = fmaxf(m.z, v.z); m.w = fmaxf(m.w, v.w);
        cnt++;
    }
    int base = cur * FD + lane * 4;
    atomicAdd(&g_psum[base + 0], s.x); atomicAdd(&g_psum[base + 1], s.y);
    atomicAdd(&g_psum[base + 2], s.z); atomicAdd(&g_psum[base + 3], s.w);
    atomicMaxF(&g_pmax[base + 0], m.x); atomicMaxF(&g_pmax[base + 1], m.y);
    atomicMaxF(&g_pmax[base + 2], m.z); atomicMaxF(&g_pmax[base + 3], m.w);
    if (lane == 0) atomicAdd(&g_pcnt[cur], cnt);
}

// ---------------- readout head ---------------------------------------------
__global__ void k_readout(const float* __restrict__ gfeat,
                          const float* __restrict__ Wg, const float* __restrict__ bg,
                          const float* __restrict__ Wo, const float* __restrict__ bo,
                          float* __restrict__ out) {
    __shared__ float flat[3 * FD];
    __shared__ float logits[2];
    int g = blockIdx.x, o = threadIdx.x;     // 128 threads
    float cnt = fmaxf((float)g_pcnt[g], 1.f);
    flat[o]       = g_psum[g * FD + o] / cnt;
    flat[FD + o]  = g_pmax[g * FD + o];
    float acc = bg[o];
#pragma unroll
    for (int k = 0; k < GF; k++) acc += gfeat[g * GF + k] * Wg[k * FD + o];
    flat[2 * FD + o] = acc;
    __syncthreads();
    if (o < 2) {
        float l = bo[o];
        for (int j = 0; j < 3 * FD; j++) l += flat[j] * Wo[j * 2 + o];
        logits[o] = l;
    }
    __syncthreads();
    if (o < 2) {
        float mm  = fmaxf(logits[0], logits[1]);
        float lse = mm + logf(expf(logits[0] - mm) + expf(logits[1] - mm));
        out[g * 2 + o] = logits[o] - lse;
    }
}

// ---------------- launch -----------------------------------------------------
extern "C" void kernel_launch(void* const* d_in, const int* in_sizes, int n_in,
                              void* d_out, int out_size) {
    const float* x     = (const float*)d_in[0];
    const int*   edges = (const int*)  d_in[1];
    const int*   batch = (const int*)  d_in[2];
    const float* gfeat = (const float*)d_in[3];
    const float* Wl0   = (const float*)d_in[4];
    const float* bl0   = (const float*)d_in[5];
    const float* Wr0   = (const float*)d_in[6];
    const float* Wl1   = (const float*)d_in[7];
    const float* bl1   = (const float*)d_in[8];
    const float* Wr1   = (const float*)d_in[9];
    const float* Wg    = (const float*)d_in[10];
    const float* bg    = (const float*)d_in[11];
    const float* Wo    = (const float*)d_in[12];
    const float* bo    = (const float*)d_in[13];
    float* out = (float*)d_out;

    cudaFuncSetAttribute(k_gemm, cudaFuncAttributeMaxDynamicSharedMemorySize,
                         GEMM_SMEM);

    __nv_bfloat16 *pUh, *pUl, *pBh, *pBl;
    __half *pXh, *pHh;
    float *p_h0, *p_h1;
    cudaGetSymbolAddress((void**)&pUh, g_Uh);
    cudaGetSymbolAddress((void**)&pUl, g_Ul);
    cudaGetSymbolAddress((void**)&pBh, g_Bh);
    cudaGetSymbolAddress((void**)&pBl, g_Bl);
    cudaGetSymbolAddress((void**)&pXh, g_Xh);
    cudaGetSymbolAddress((void**)&pHh, g_Hh);
    cudaGetSymbolAddress((void**)&p_h0, g_h0);
    cudaGetSymbolAddress((void**)&p_h1, g_h1);

    const int scan_nb = (NN + SCAN_B - 1) / SCAN_B;   // 98
    const int gemm_nb = (NN + 127) / 128;             // 782

    k_init<<<(NN + 255) / 256, 256>>>();
    k_hist<<<(NE + 255) / 256, 256>>>(edges);
    k_scanA<<<scan_nb, SCAN_B>>>();
    k_scanB<<<1, 128>>>(scan_nb);
    k_scanC<<<scan_nb, SCAN_B>>>();
    k_fillcol<<<(NE + 255) / 256, 256>>>(edges);

    k_prepw<<<256, 256>>>(Wr0, Wl0, Wr1, Wl1);
    k_split_x<<<(NN * 32 + 255) / 256, 256>>>(x);

    // layer 0: gather fp16 x; GEMM writes h0 + bf16 split + fp16 mirror
    k_aggregate<<<(NN + 7) / 8, 256>>>(pXh);
    k_gemm<<<gemm_nb, 256, GEMM_SMEM>>>(pUh, pUl, pBh, pBl, bl0, p_h0,
                                        pUh, pUl, pHh, 1, 1);
    // layer 1: gather fp16 h0; plain GEMM to h1
    k_aggregate<<<(NN + 7) / 8, 256>>>(pHh);
    k_gemm<<<gemm_nb, 256, GEMM_SMEM>>>(pUh, pUl, pBh + 32768, pBl + 32768, bl1,
                                        p_h1, nullptr, nullptr, nullptr, 0, 0);

    // pooling + head
    int pool_warps  = (NN + 63) / 64;
    int pool_blocks = (pool_warps * 32 + 255) / 256;
    k_pool<<<pool_blocks, 256>>>(p_h1, batch);
    k_readout<<<NG, FD>>>(gfeat, Wg, bg, Wo, bo, out);
}

// round 9
// speedup vs baseline: 1.5809x; 1.1775x over previous
#include <cuda_runtime.h>
#include <cuda_fp16.h>
#include <cstdint>
#include <math.h>

#define NN 100000
#define NE 1600000
#define FD 128
#define NG 128
#define GF 32

// ---------------- scratch (device globals; no allocations allowed) ----------
__device__ __align__(16) __half g_Uh[(size_t)NN * 256];   // [X|AGG] fp16 hi
__device__ __align__(16) __half g_Ul[(size_t)NN * 256];   // [X|AGG] fp16 lo
__device__ __align__(16) __half g_B [2 * 128 * 256];      // W^T fp16, per layer
__device__ __align__(16) float g_h1[(size_t)NN * FD];
__device__ int   g_deg[NN];
__device__ int   g_rowptr[NN + 1];
__device__ int   g_fill[NN];
__device__ int   g_col[NE];
__device__ float g_psum[NG * FD];
__device__ float g_pmax[NG * FD];
__device__ int   g_pcnt[NG];
__device__ int   g_bsum[128];

// ---------------- small helpers ---------------------------------------------
__device__ __forceinline__ void atomicMaxF(float* addr, float v) {
    if (v >= 0.f) atomicMax((int*)addr, __float_as_int(v));
    else          atomicMin((unsigned int*)addr, __float_as_uint(v));
}

__device__ __forceinline__ void hsplit(float v, __half& hi, __half& lo) {
    hi = __float2half_rn(v);
    lo = __float2half_rn(v - __half2float(hi));
}

__device__ __forceinline__ uint32_t smem_u32(const void* p) {
    uint32_t a;
    asm("{ .reg .u64 t; cvta.to.shared.u64 t, %1; cvt.u32.u64 %0, t; }"
        : "=r"(a) : "l"(p));
    return a;
}

__device__ __forceinline__ void ldsm4(uint32_t* r, uint32_t addr) {
    asm volatile("ldmatrix.sync.aligned.m8n8.x4.shared.b16 {%0,%1,%2,%3}, [%4];"
                 : "=r"(r[0]), "=r"(r[1]), "=r"(r[2]), "=r"(r[3]) : "r"(addr));
}
__device__ __forceinline__ void ldsm2(uint32_t* r, uint32_t addr) {
    asm volatile("ldmatrix.sync.aligned.m8n8.x2.shared.b16 {%0,%1}, [%2];"
                 : "=r"(r[0]), "=r"(r[1]) : "r"(addr));
}
__device__ __forceinline__ void mma_f16(float* c, const uint32_t* a, const uint32_t* b) {
    asm volatile(
        "mma.sync.aligned.m16n8k16.row.col.f32.f16.f16.f32 "
        "{%0,%1,%2,%3}, {%4,%5,%6,%7}, {%8,%9}, {%0,%1,%2,%3};"
        : "+f"(c[0]), "+f"(c[1]), "+f"(c[2]), "+f"(c[3])
        : "r"(a[0]), "r"(a[1]), "r"(a[2]), "r"(a[3]), "r"(b[0]), "r"(b[1]));
}

// ---------------- CSR build -------------------------------------------------
__global__ void k_init() {
    int i = blockIdx.x * blockDim.x + threadIdx.x;
    if (i < NN) { g_deg[i] = 0; g_fill[i] = 0; }
    if (i < NG * FD) { g_psum[i] = 0.f; g_pmax[i] = -INFINITY; }
    if (i < NG) g_pcnt[i] = 0;
}

__global__ void k_hist(const int* __restrict__ edges) {
    int e = blockIdx.x * blockDim.x + threadIdx.x;
    if (e < NE) atomicAdd(&g_deg[edges[NE + e]], 1);
}

#define SCAN_B 1024
__global__ void k_scanA() {
    __shared__ int sm[SCAN_B];
    int i = blockIdx.x * SCAN_B + threadIdx.x;
    int v = (i < NN) ? g_deg[i] : 0;
    sm[threadIdx.x] = v;
    __syncthreads();
    for (int off = 1; off < SCAN_B; off <<= 1) {
        int t = (threadIdx.x >= off) ? sm[threadIdx.x - off] : 0;
        __syncthreads();
        sm[threadIdx.x] += t;
        __syncthreads();
    }
    if (i < NN) g_rowptr[i] = sm[threadIdx.x] - v;   // exclusive
    if (threadIdx.x == SCAN_B - 1) g_bsum[blockIdx.x] = sm[SCAN_B - 1];
}

__global__ void k_scanB(int nb) {                    // parallel Kogge-Stone
    __shared__ int s[128];
    int t = threadIdx.x;
    int v = (t < nb) ? g_bsum[t] : 0;
    s[t] = v;
    __syncthreads();
    for (int off = 1; off < 128; off <<= 1) {
        int u = (t >= off) ? s[t - off] : 0;
        __syncthreads();
        s[t] += u;
        __syncthreads();
    }
    if (t < nb) g_bsum[t] = s[t] - v;                // exclusive
}

__global__ void k_scanC() {
    int i = blockIdx.x * SCAN_B + threadIdx.x;
    if (i < NN) g_rowptr[i] += g_bsum[blockIdx.x];
    if (i == 0) g_rowptr[NN] = NE;
}

__global__ void k_fillcol(const int* __restrict__ edges) {
    int e = blockIdx.x * blockDim.x + threadIdx.x;
    if (e < NE) {
        int t = edges[NE + e];
        int p = g_rowptr[t] + atomicAdd(&g_fill[t], 1);
        g_col[p] = edges[e];
    }
}

// ---------------- weight prep: V = [Wr;Wl] -> B[n][k] fp16 ------------------
__global__ void k_prepw(const float* __restrict__ Wr0, const float* __restrict__ Wl0,
                        const float* __restrict__ Wr1, const float* __restrict__ Wl1) {
    int idx = blockIdx.x * 256 + threadIdx.x;        // 65536 total
    int L = idx >> 15;
    int rem = idx & 32767;
    int k = rem >> 7, n = rem & 127;
    const float* Wr = L ? Wr1 : Wr0;
    const float* Wl = L ? Wl1 : Wl0;
    float v = (k < FD) ? Wr[k * FD + n] : Wl[(k - FD) * FD + n];
    g_B[L * 32768 + n * 256 + k] = __float2half_rn(v);
}

// ---------------- split X into fp16 hi/lo (U cols 0..127) -------------------
__global__ void k_split_x(const float* __restrict__ X) {
    int i = blockIdx.x * 256 + threadIdx.x;          // over NN*32 float4
    if (i >= NN * 32) return;
    float4 v = ((const float4*)X)[i];
    int node = i >> 5, q = (i & 31) * 4;
    union { __half s[4]; uint2 u; } ph, pl;
    hsplit(v.x, ph.s[0], pl.s[0]);
    hsplit(v.y, ph.s[1], pl.s[1]);
    hsplit(v.z, ph.s[2], pl.s[2]);
    hsplit(v.w, ph.s[3], pl.s[3]);
    *(uint2*)(g_Uh + (size_t)node * 256 + q) = ph.u;
    *(uint2*)(g_Ul + (size_t)node * 256 + q) = pl.u;
}

// ---------------- neighbor mean aggregation -----------------------------------
// Gathers fp16 hi rows from g_Uh cols 0..127 (512B row stride, 256B payload),
// accumulates fp32, writes fp16 hi/lo of mean to U cols 128..255.
__global__ void k_aggregate() {
    int node = blockIdx.x * 8 + (threadIdx.x >> 5);
    int lane = threadIdx.x & 31;
    if (node >= NN) return;
    int beg = g_rowptr[node], end = g_rowptr[node + 1];
    const uint2* Hv = (const uint2*)g_Uh;            // 4 halves per lane
    float4 s = make_float4(0.f, 0.f, 0.f, 0.f);
    int e = beg;
    for (; e + 3 < end; e += 4) {
        int i0 = g_col[e], i1 = g_col[e + 1], i2 = g_col[e + 2], i3 = g_col[e + 3];
        uint2 u0 = Hv[(size_t)i0 * 64 + lane];
        uint2 u1 = Hv[(size_t)i1 * 64 + lane];
        uint2 u2 = Hv[(size_t)i2 * 64 + lane];
        uint2 u3 = Hv[(size_t)i3 * 64 + lane];
        float2 a0 = __half22float2(*(__half2*)&u0.x), a1 = __half22float2(*(__half2*)&u0.y);
        float2 b0 = __half22float2(*(__half2*)&u1.x), b1 = __half22float2(*(__half2*)&u1.y);
        float2 c0 = __half22float2(*(__half2*)&u2.x), c1 = __half22float2(*(__half2*)&u2.y);
        float2 d0 = __half22float2(*(__half2*)&u3.x), d1 = __half22float2(*(__half2*)&u3.y);
        s.x += (a0.x + b0.x) + (c0.x + d0.x);
        s.y += (a0.y + b0.y) + (c0.y + d0.y);
        s.z += (a1.x + b1.x) + (c1.x + d1.x);
        s.w += (a1.y + b1.y) + (c1.y + d1.y);
    }
    for (; e < end; e++) {
        uint2 u = Hv[(size_t)g_col[e] * 64 + lane];
        float2 f0 = __half22float2(*(__half2*)&u.x), f1 = __half22float2(*(__half2*)&u.y);
        s.x += f0.x; s.y += f0.y; s.z += f1.x; s.w += f1.y;
    }
    float sc = 1.f / fmaxf((float)(end - beg), 1.f);
    union { __half s[4]; uint2 u; } ph, pl;
    hsplit(s.x * sc, ph.s[0], pl.s[0]);
    hsplit(s.y * sc, ph.s[1], pl.s[1]);
    hsplit(s.z * sc, ph.s[2], pl.s[2]);
    hsplit(s.w * sc, ph.s[3], pl.s[3]);
    size_t off = (size_t)node * 256 + 128 + lane * 4;
    *(uint2*)(g_Uh + off) = ph.u;
    *(uint2*)(g_Ul + off) = pl.u;
}

// ---------------- mma.sync GEMM: fp16 A-split x fp16 B (2-term) -------------
// CTA: 128 nodes x 128 outs; 8 warps 2(M)x4(N); warp tile 64x32; K=256 by 64.
// acc = Uh@B + Ul@B; B = fp16(W) (single tile). 3 smem tiles.
#define TP 72
#define TILE_B (128 * TP * 2)                 // 18432 bytes per tile
#define GEMM_SMEM (3 * TILE_B + 512)

__device__ __forceinline__ void load_chunk(__half* dst,
                                           const __half* __restrict__ src,
                                           int row0, int rowmax, int kofs) {
    for (int i = threadIdx.x; i < 1024; i += 256) {  // uint4 units (8 fp16)
        int r = i >> 3, q = i & 7;
        int gr = row0 + r;
        uint4 v = make_uint4(0, 0, 0, 0);
        if (gr < rowmax) v = *(const uint4*)(src + (size_t)gr * 256 + kofs + q * 8);
        *(uint4*)(dst + r * TP + q * 8) = v;
    }
}

__global__ __launch_bounds__(256, 2) void k_gemm(
    const __half* __restrict__ Uh, const __half* __restrict__ Ul,
    const __half* __restrict__ B, const float* __restrict__ bias,
    float* __restrict__ OUT,
    __half* __restrict__ NUh, __half* __restrict__ NUl,
    int relu, int wsplit)
{
    extern __shared__ char smem[];
    __half* sUh = (__half*)smem;
    __half* sUl = (__half*)(smem + TILE_B);
    __half* sB  = (__half*)(smem + 2 * TILE_B);
    float* sbias = (float*)(smem + 3 * TILE_B);

    const int tid = threadIdx.x, wid = tid >> 5, lid = tid & 31;
    const int wm = wid >> 2, wn = wid & 3;
    const int node0 = blockIdx.x * 128;

    if (tid < FD) sbias[tid] = bias[tid];

    float acc[4][4][4];
#pragma unroll
    for (int mt = 0; mt < 4; mt++)
#pragma unroll
        for (int nt = 0; nt < 4; nt++)
#pragma unroll
            for (int j = 0; j < 4; j++) acc[mt][nt][j] = 0.f;

    uint32_t aUh = smem_u32(sUh), aUl = smem_u32(sUl);
    uint32_t aB  = smem_u32(sB);
    const uint32_t a_lane = (uint32_t)((lid & 15) * (TP * 2) + ((lid >> 4) << 4));
    const uint32_t b_lane = (uint32_t)((lid & 7) * (TP * 2) + (((lid >> 3) & 1) << 4));

    for (int c = 0; c < 4; c++) {
        load_chunk(sUh, Uh, node0, NN, c * 64);
        load_chunk(sUl, Ul, node0, NN, c * 64);
        load_chunk(sB,  B,  0, 128, c * 64);
        __syncthreads();
#pragma unroll
        for (int ks = 0; ks < 4; ks++) {
            uint32_t ah[4][4], al[4][4];
#pragma unroll
            for (int mt = 0; mt < 4; mt++) {
                uint32_t roff = (uint32_t)((wm * 64 + mt * 16) * (TP * 2) + ks * 32);
                ldsm4(ah[mt], aUh + roff + a_lane);
                ldsm4(al[mt], aUl + roff + a_lane);
            }
#pragma unroll
            for (int nt = 0; nt < 4; nt++) {
                uint32_t bb[2];
                uint32_t roff = (uint32_t)((wn * 32 + nt * 8) * (TP * 2) + ks * 32);
                ldsm2(bb, aB + roff + b_lane);
#pragma unroll
                for (int mt = 0; mt < 4; mt++) {
                    mma_f16(acc[mt][nt], ah[mt], bb);
                    mma_f16(acc[mt][nt], al[mt], bb);
                }
            }
        }
        __syncthreads();
    }

    // epilogue: c-fragment (row = t/4 [+8], col = 2*(t%4) [+1])
    const int tq = lid >> 2, tr = lid & 3;
#pragma unroll
    for (int mt = 0; mt < 4; mt++) {
#pragma unroll
        for (int h = 0; h < 2; h++) {
            int node = node0 + wm * 64 + mt * 16 + tq + h * 8;
            if (node >= NN) continue;
#pragma unroll
            for (int nt = 0; nt < 4; nt++) {
                int col = wn * 32 + nt * 8 + tr * 2;
                float v0 = acc[mt][nt][h * 2 + 0] + sbias[col];
                float v1 = acc[mt][nt][h * 2 + 1] + sbias[col + 1];
                if (relu) { v0 = fmaxf(v0, 0.f); v1 = fmaxf(v1, 0.f); }
                if (wsplit) {
                    // layer 0: store h0 only as fp16 hi/lo into U cols 0..127
                    union { __half s[2]; uint32_t u; } ph, pl;
                    hsplit(v0, ph.s[0], pl.s[0]);
                    hsplit(v1, ph.s[1], pl.s[1]);
                    *(uint32_t*)(NUh + (size_t)node * 256 + col) = ph.u;
                    *(uint32_t*)(NUl + (size_t)node * 256 + col) = pl.u;
                } else {
                    *(float2*)(OUT + (size_t)node * FD + col) = make_float2(v0, v1);
                }
            }
        }
    }
}

// ---------------- pooling (sorted batch_idx, warp-local segments) -----------
__global__ void k_pool(const float* __restrict__ H, const int* __restrict__ batch) {
    int wg   = (blockIdx.x * blockDim.x + threadIdx.x) >> 5;
    int lane = threadIdx.x & 31;
    int n0 = wg * 64;
    if (n0 >= NN) return;
    int n1 = min(n0 + 64, NN);
    const float4* Hv = (const float4*)H;
    float4 s = make_float4(0.f, 0.f, 0.f, 0.f);
    float4 m = make_float4(-INFINITY, -INFINITY, -INFINITY, -INFINITY);
    int cnt = 0, cur = batch[n0];
    for (int n = n0; n < n1; n++) {
        int g = batch[n];
        if (g != cur) {
            int base = cur * FD + lane * 4;
            atomicAdd(&g_psum[base + 0], s.x); atomicAdd(&g_psum[base + 1], s.y);
            atomicAdd(&g_psum[base + 2], s.z); atomicAdd(&g_psum[base + 3], s.w);
            atomicMaxF(&g_pmax[base + 0], m.x); atomicMaxF(&g_pmax[base + 1], m.y);
            atomicMaxF(&g_pmax[base + 2], m.z); atomicMaxF(&g_pmax[base + 3], m.w);
            if (lane == 0) atomicAdd(&g_pcnt[cur], cnt);
            s = make_float4(0.f, 0.f, 0.f, 0.f);
            m = make_float4(-INFINITY, -INFINITY, -INFINITY, -INFINITY);
            cnt = 0; cur = g;
        }
        float4 v = Hv[(size_t)n * 32 + lane];
        s.x += v.x; s.y += v.y; s.z += v.z; s.w += v.w;
        m.x = fmaxf(m.x, v.x); m.y = fmaxf(m.y, v.y);
        m.z = fmaxf(m.z, v.z); m.w = fmaxf(m.w, v.w);
        cnt++;
    }
    int base = cur * FD + lane * 4;
    atomicAdd(&g_psum[base + 0], s.x); atomicAdd(&g_psum[base + 1], s.y);
    atomicAdd(&g_psum[base + 2], s.z); atomicAdd(&g_psum[base + 3], s.w);
    atomicMaxF(&g_pmax[base + 0], m.x); atomicMaxF(&g_pmax[base + 1], m.y);
    atomicMaxF(&g_pmax[base + 2], m.z); atomicMaxF(&g_pmax[base + 3], m.w);
    if (lane == 0) atomicAdd(&g_pcnt[cur], cnt);
}

// ---------------- readout head ---------------------------------------------
__global__ void k_readout(const float* __restrict__ gfeat,
                          const float* __restrict__ Wg, const float* __restrict__ bg,
                          const float* __restrict__ Wo, const float* __restrict__ bo,
                          float* __restrict__ out) {
    __shared__ float flat[3 * FD];
    __shared__ float logits[2];
    int g = blockIdx.x, o = threadIdx.x;     // 128 threads
    float cnt = fmaxf((float)g_pcnt[g], 1.f);
    flat[o]       = g_psum[g * FD + o] / cnt;
    flat[FD + o]  = g_pmax[g * FD + o];
    float acc = bg[o];
#pragma unroll
    for (int k = 0; k < GF; k++) acc += gfeat[g * GF + k] * Wg[k * FD + o];
    flat[2 * FD + o] = acc;
    __syncthreads();
    if (o < 2) {
        float l = bo[o];
        for (int j = 0; j < 3 * FD; j++) l += flat[j] * Wo[j * 2 + o];
        logits[o] = l;
    }
    __syncthreads();
    if (o < 2) {
        float mm  = fmaxf(logits[0], logits[1]);
        float lse = mm + logf(expf(logits[0] - mm) + expf(logits[1] - mm));
        out[g * 2 + o] = logits[o] - lse;
    }
}

// ---------------- launch -----------------------------------------------------
extern "C" void kernel_launch(void* const* d_in, const int* in_sizes, int n_in,
                              void* d_out, int out_size) {
    const float* x     = (const float*)d_in[0];
    const int*   edges = (const int*)  d_in[1];
    const int*   batch = (const int*)  d_in[2];
    const float* gfeat = (const float*)d_in[3];
    const float* Wl0   = (const float*)d_in[4];
    const float* bl0   = (const float*)d_in[5];
    const float* Wr0   = (const float*)d_in[6];
    const float* Wl1   = (const float*)d_in[7];
    const float* bl1   = (const float*)d_in[8];
    const float* Wr1   = (const float*)d_in[9];
    const float* Wg    = (const float*)d_in[10];
    const float* bg    = (const float*)d_in[11];
    const float* Wo    = (const float*)d_in[12];
    const float* bo    = (const float*)d_in[13];
    float* out = (float*)d_out;

    cudaFuncSetAttribute(k_gemm, cudaFuncAttributeMaxDynamicSharedMemorySize,
                         GEMM_SMEM);

    __half *pUh, *pUl, *pB;
    float *p_h1;
    cudaGetSymbolAddress((void**)&pUh, g_Uh);
    cudaGetSymbolAddress((void**)&pUl, g_Ul);
    cudaGetSymbolAddress((void**)&pB,  g_B);
    cudaGetSymbolAddress((void**)&p_h1, g_h1);

    const int scan_nb = (NN + SCAN_B - 1) / SCAN_B;   // 98
    const int gemm_nb = (NN + 127) / 128;             // 782

    k_init<<<(NN + 255) / 256, 256>>>();
    k_hist<<<(NE + 255) / 256, 256>>>(edges);
    k_scanA<<<scan_nb, SCAN_B>>>();
    k_scanB<<<1, 128>>>(scan_nb);
    k_scanC<<<scan_nb, SCAN_B>>>();
    k_fillcol<<<(NE + 255) / 256, 256>>>(edges);

    k_prepw<<<256, 256>>>(Wr0, Wl0, Wr1, Wl1);
    k_split_x<<<(NN * 32 + 255) / 256, 256>>>(x);

    // layer 0: gather fp16 x (U cols 0..127); GEMM writes h0 fp16 hi/lo in place
    k_aggregate<<<(NN + 7) / 8, 256>>>();
    k_gemm<<<gemm_nb, 256, GEMM_SMEM>>>(pUh, pUl, pB, bl0, nullptr,
                                        pUh, pUl, 1, 1);
    // layer 1: gather fp16 h0; GEMM writes fp32 h1
    k_aggregate<<<(NN + 7) / 8, 256>>>();
    k_gemm<<<gemm_nb, 256, GEMM_SMEM>>>(pUh, pUl, pB + 32768, bl1, p_h1,
                                        nullptr, nullptr, 0, 0);

    // pooling + head
    int pool_warps  = (NN + 63) / 64;
    int pool_blocks = (pool_warps * 32 + 255) / 256;
    k_pool<<<pool_blocks, 256>>>(p_h1, batch);
    k_readout<<<NG, FD>>>(gfeat, Wg, bg, Wo, bo, out);
}

// round 10
// speedup vs baseline: 2.1508x; 1.3605x over previous
#include <cuda_runtime.h>
#include <cuda_fp16.h>
#include <cstdint>
#include <math.h>

#define NN 100000
#define NE 1600000
#define FD 128
#define NG 128
#define GF 32

// ---------------- scratch (device globals; no allocations allowed) ----------
__device__ __align__(16) __half g_U[(size_t)NN * 256];    // [X|AGG] fp16
__device__ __align__(16) __half g_B[2 * 128 * 256];       // W^T fp16, per layer
__device__ __align__(16) float g_h1[(size_t)NN * FD];
__device__ int   g_deg[NN];
__device__ int   g_rowptr[NN + 1];
__device__ int   g_fill[NN];
__device__ int   g_col[NE];
__device__ float g_psum[NG * FD];
__device__ float g_pmax[NG * FD];
__device__ int   g_pcnt[NG];
__device__ int   g_bsum[128];

// ---------------- small helpers ---------------------------------------------
__device__ __forceinline__ void atomicMaxF(float* addr, float v) {
    if (v >= 0.f) atomicMax((int*)addr, __float_as_int(v));
    else          atomicMin((unsigned int*)addr, __float_as_uint(v));
}

__device__ __forceinline__ uint32_t smem_u32(const void* p) {
    uint32_t a;
    asm("{ .reg .u64 t; cvta.to.shared.u64 t, %1; cvt.u32.u64 %0, t; }"
        : "=r"(a) : "l"(p));
    return a;
}

__device__ __forceinline__ void ldsm4(uint32_t* r, uint32_t addr) {
    asm volatile("ldmatrix.sync.aligned.m8n8.x4.shared.b16 {%0,%1,%2,%3}, [%4];"
                 : "=r"(r[0]), "=r"(r[1]), "=r"(r[2]), "=r"(r[3]) : "r"(addr));
}
__device__ __forceinline__ void ldsm2(uint32_t* r, uint32_t addr) {
    asm volatile("ldmatrix.sync.aligned.m8n8.x2.shared.b16 {%0,%1}, [%2];"
                 : "=r"(r[0]), "=r"(r[1]) : "r"(addr));
}
__device__ __forceinline__ void mma_f16(float* c, const uint32_t* a, const uint32_t* b) {
    asm volatile(
        "mma.sync.aligned.m16n8k16.row.col.f32.f16.f16.f32 "
        "{%0,%1,%2,%3}, {%4,%5,%6,%7}, {%8,%9}, {%0,%1,%2,%3};"
        : "+f"(c[0]), "+f"(c[1]), "+f"(c[2]), "+f"(c[3])
        : "r"(a[0]), "r"(a[1]), "r"(a[2]), "r"(a[3]), "r"(b[0]), "r"(b[1]));
}

// ---------------- CSR build -------------------------------------------------
__global__ void k_init() {
    int i = blockIdx.x * blockDim.x + threadIdx.x;
    if (i < NN) { g_deg[i] = 0; g_fill[i] = 0; }
    if (i < NG * FD) { g_psum[i] = 0.f; g_pmax[i] = -INFINITY; }
    if (i < NG) g_pcnt[i] = 0;
}

__global__ void k_hist(const int* __restrict__ edges) {
    int e = blockIdx.x * blockDim.x + threadIdx.x;
    if (e < NE) atomicAdd(&g_deg[edges[NE + e]], 1);
}

#define SCAN_B 1024
__global__ void k_scanA() {
    __shared__ int sm[SCAN_B];
    int i = blockIdx.x * SCAN_B + threadIdx.x;
    int v = (i < NN) ? g_deg[i] : 0;
    sm[threadIdx.x] = v;
    __syncthreads();
    for (int off = 1; off < SCAN_B; off <<= 1) {
        int t = (threadIdx.x >= off) ? sm[threadIdx.x - off] : 0;
        __syncthreads();
        sm[threadIdx.x] += t;
        __syncthreads();
    }
    if (i < NN) g_rowptr[i] = sm[threadIdx.x] - v;   // exclusive
    if (threadIdx.x == SCAN_B - 1) g_bsum[blockIdx.x] = sm[SCAN_B - 1];
}

__global__ void k_scanB(int nb) {                    // parallel Kogge-Stone
    __shared__ int s[128];
    int t = threadIdx.x;
    int v = (t < nb) ? g_bsum[t] : 0;
    s[t] = v;
    __syncthreads();
    for (int off = 1; off < 128; off <<= 1) {
        int u = (t >= off) ? s[t - off] : 0;
        __syncthreads();
        s[t] += u;
        __syncthreads();
    }
    if (t < nb) g_bsum[t] = s[t] - v;                // exclusive
}

__global__ void k_scanC() {
    int i = blockIdx.x * SCAN_B + threadIdx.x;
    if (i < NN) g_rowptr[i] += g_bsum[blockIdx.x];
    if (i == 0) g_rowptr[NN] = NE;
}

__global__ void k_fillcol(const int* __restrict__ edges) {
    int e = blockIdx.x * blockDim.x + threadIdx.x;
    if (e < NE) {
        int t = edges[NE + e];
        int p = g_rowptr[t] + atomicAdd(&g_fill[t], 1);
        g_col[p] = edges[e];
    }
}

// ---------------- weight prep: V = [Wr;Wl] -> B[n][k] fp16 ------------------
__global__ void k_prepw(const float* __restrict__ Wr0, const float* __restrict__ Wl0,
                        const float* __restrict__ Wr1, const float* __restrict__ Wl1) {
    int idx = blockIdx.x * 256 + threadIdx.x;        // 65536 total
    int L = idx >> 15;
    int rem = idx & 32767;
    int k = rem >> 7, n = rem & 127;
    const float* Wr = L ? Wr1 : Wr0;
    const float* Wl = L ? Wl1 : Wl0;
    float v = (k < FD) ? Wr[k * FD + n] : Wl[(k - FD) * FD + n];
    g_B[L * 32768 + n * 256 + k] = __float2half_rn(v);
}

// ---------------- split X into fp16 (U cols 0..127) -------------------------
__global__ void k_split_x(const float* __restrict__ X) {
    int i = blockIdx.x * 256 + threadIdx.x;          // over NN*32 float4
    if (i >= NN * 32) return;
    float4 v = ((const float4*)X)[i];
    int node = i >> 5, q = (i & 31) * 4;
    union { __half2 h2[2]; uint2 u; } hh;
    hh.h2[0] = __floats2half2_rn(v.x, v.y);
    hh.h2[1] = __floats2half2_rn(v.z, v.w);
    *(uint2*)(g_U + (size_t)node * 256 + q) = hh.u;
}

// ---------------- neighbor mean aggregation ----------------------------------
// Gathers fp16 rows from g_U cols 0..127 (512B stride, 256B payload),
// accumulates fp32, writes fp16 mean to U cols 128..255.
__global__ void k_aggregate() {
    int node = blockIdx.x * 8 + (threadIdx.x >> 5);
    int lane = threadIdx.x & 31;
    if (node >= NN) return;
    int beg = g_rowptr[node], end = g_rowptr[node + 1];
    const uint2* Hv = (const uint2*)g_U;             // 4 halves per lane
    float4 s = make_float4(0.f, 0.f, 0.f, 0.f);
    int e = beg;
    for (; e + 3 < end; e += 4) {
        int i0 = g_col[e], i1 = g_col[e + 1], i2 = g_col[e + 2], i3 = g_col[e + 3];
        uint2 u0 = Hv[(size_t)i0 * 64 + lane];
        uint2 u1 = Hv[(size_t)i1 * 64 + lane];
        uint2 u2 = Hv[(size_t)i2 * 64 + lane];
        uint2 u3 = Hv[(size_t)i3 * 64 + lane];
        float2 a0 = __half22float2(*(__half2*)&u0.x), a1 = __half22float2(*(__half2*)&u0.y);
        float2 b0 = __half22float2(*(__half2*)&u1.x), b1 = __half22float2(*(__half2*)&u1.y);
        float2 c0 = __half22float2(*(__half2*)&u2.x), c1 = __half22float2(*(__half2*)&u2.y);
        float2 d0 = __half22float2(*(__half2*)&u3.x), d1 = __half22float2(*(__half2*)&u3.y);
        s.x += (a0.x + b0.x) + (c0.x + d0.x);
        s.y += (a0.y + b0.y) + (c0.y + d0.y);
        s.z += (a1.x + b1.x) + (c1.x + d1.x);
        s.w += (a1.y + b1.y) + (c1.y + d1.y);
    }
    for (; e < end; e++) {
        uint2 u = Hv[(size_t)g_col[e] * 64 + lane];
        float2 f0 = __half22float2(*(__half2*)&u.x), f1 = __half22float2(*(__half2*)&u.y);
        s.x += f0.x; s.y += f0.y; s.z += f1.x; s.w += f1.y;
    }
    float sc = 1.f / fmaxf((float)(end - beg), 1.f);
    union { __half2 h2[2]; uint2 u; } hh;
    hh.h2[0] = __floats2half2_rn(s.x * sc, s.y * sc);
    hh.h2[1] = __floats2half2_rn(s.z * sc, s.w * sc);
    *(uint2*)(g_U + (size_t)node * 256 + 128 + lane * 4) = hh.u;
}

// ---------------- mma.sync GEMM: fp16 A x fp16 B (single term) --------------
// CTA: 128 nodes x 128 outs; 8 warps 2(M)x4(N); warp tile 64x32; K=256 by 64.
#define TP 72
#define TILE_B (128 * TP * 2)                 // 18432 bytes per tile
#define GEMM_SMEM (2 * TILE_B + 512)

__device__ __forceinline__ void load_chunk(__half* dst,
                                           const __half* __restrict__ src,
                                           int row0, int rowmax, int kofs) {
    for (int i = threadIdx.x; i < 1024; i += 256) {  // uint4 units (8 fp16)
        int r = i >> 3, q = i & 7;
        int gr = row0 + r;
        uint4 v = make_uint4(0, 0, 0, 0);
        if (gr < rowmax) v = *(const uint4*)(src + (size_t)gr * 256 + kofs + q * 8);
        *(uint4*)(dst + r * TP + q * 8) = v;
    }
}

__global__ __launch_bounds__(256, 2) void k_gemm(
    const __half* __restrict__ U, const __half* __restrict__ B,
    const float* __restrict__ bias, float* __restrict__ OUT,
    __half* __restrict__ NU, int relu, int wsplit)
{
    extern __shared__ char smem[];
    __half* sU = (__half*)smem;
    __half* sB = (__half*)(smem + TILE_B);
    float* sbias = (float*)(smem + 2 * TILE_B);

    const int tid = threadIdx.x, wid = tid >> 5, lid = tid & 31;
    const int wm = wid >> 2, wn = wid & 3;
    const int node0 = blockIdx.x * 128;

    if (tid < FD) sbias[tid] = bias[tid];

    float acc[4][4][4];
#pragma unroll
    for (int mt = 0; mt < 4; mt++)
#pragma unroll
        for (int nt = 0; nt < 4; nt++)
#pragma unroll
            for (int j = 0; j < 4; j++) acc[mt][nt][j] = 0.f;

    uint32_t aU = smem_u32(sU), aB = smem_u32(sB);
    const uint32_t a_lane = (uint32_t)((lid & 15) * (TP * 2) + ((lid >> 4) << 4));
    const uint32_t b_lane = (uint32_t)((lid & 7) * (TP * 2) + (((lid >> 3) & 1) << 4));

    for (int c = 0; c < 4; c++) {
        load_chunk(sU, U, node0, NN, c * 64);
        load_chunk(sB, B, 0, 128, c * 64);
        __syncthreads();
#pragma unroll
        for (int ks = 0; ks < 4; ks++) {
            uint32_t ah[4][4];
#pragma unroll
            for (int mt = 0; mt < 4; mt++) {
                uint32_t roff = (uint32_t)((wm * 64 + mt * 16) * (TP * 2) + ks * 32);
                ldsm4(ah[mt], aU + roff + a_lane);
            }
#pragma unroll
            for (int nt = 0; nt < 4; nt++) {
                uint32_t bb[2];
                uint32_t roff = (uint32_t)((wn * 32 + nt * 8) * (TP * 2) + ks * 32);
                ldsm2(bb, aB + roff + b_lane);
#pragma unroll
                for (int mt = 0; mt < 4; mt++)
                    mma_f16(acc[mt][nt], ah[mt], bb);
            }
        }
        __syncthreads();
    }

    // epilogue: c-fragment (row = t/4 [+8], col = 2*(t%4) [+1])
    const int tq = lid >> 2, tr = lid & 3;
#pragma unroll
    for (int mt = 0; mt < 4; mt++) {
#pragma unroll
        for (int h = 0; h < 2; h++) {
            int node = node0 + wm * 64 + mt * 16 + tq + h * 8;
            if (node >= NN) continue;
#pragma unroll
            for (int nt = 0; nt < 4; nt++) {
                int col = wn * 32 + nt * 8 + tr * 2;
                float v0 = acc[mt][nt][h * 2 + 0] + sbias[col];
                float v1 = acc[mt][nt][h * 2 + 1] + sbias[col + 1];
                if (relu) { v0 = fmaxf(v0, 0.f); v1 = fmaxf(v1, 0.f); }
                if (wsplit) {
                    // layer 0: store h0 as fp16 into U cols 0..127
                    union { __half2 h2; uint32_t u; } hh;
                    hh.h2 = __floats2half2_rn(v0, v1);
                    *(uint32_t*)(NU + (size_t)node * 256 + col) = hh.u;
                } else {
                    *(float2*)(OUT + (size_t)node * FD + col) = make_float2(v0, v1);
                }
            }
        }
    }
}

// ---------------- pooling (sorted batch_idx, warp-local segments) -----------
__global__ void k_pool(const float* __restrict__ H, const int* __restrict__ batch) {
    int wg   = (blockIdx.x * blockDim.x + threadIdx.x) >> 5;
    int lane = threadIdx.x & 31;
    int n0 = wg * 64;
    if (n0 >= NN) return;
    int n1 = min(n0 + 64, NN);
    const float4* Hv = (const float4*)H;
    float4 s = make_float4(0.f, 0.f, 0.f, 0.f);
    float4 m = make_float4(-INFINITY, -INFINITY, -INFINITY, -INFINITY);
    int cnt = 0, cur = batch[n0];
    for (int n = n0; n < n1; n++) {
        int g = batch[n];
        if (g != cur) {
            int base = cur * FD + lane * 4;
            atomicAdd(&g_psum[base + 0], s.x); atomicAdd(&g_psum[base + 1], s.y);
            atomicAdd(&g_psum[base + 2], s.z); atomicAdd(&g_psum[base + 3], s.w);
            atomicMaxF(&g_pmax[base + 0], m.x); atomicMaxF(&g_pmax[base + 1], m.y);
            atomicMaxF(&g_pmax[base + 2], m.z); atomicMaxF(&g_pmax[base + 3], m.w);
            if (lane == 0) atomicAdd(&g_pcnt[cur], cnt);
            s = make_float4(0.f, 0.f, 0.f, 0.f);
            m = make_float4(-INFINITY, -INFINITY, -INFINITY, -INFINITY);
            cnt = 0; cur = g;
        }
        float4 v = Hv[(size_t)n * 32 + lane];
        s.x += v.x; s.y += v.y; s.z += v.z; s.w += v.w;
        m.x = fmaxf(m.x, v.x); m.y = fmaxf(m.y, v.y);
        m.z = fmaxf(m.z, v.z); m.w = fmaxf(m.w, v.w);
        cnt++;
    }
    int base = cur * FD + lane * 4;
    atomicAdd(&g_psum[base + 0], s.x); atomicAdd(&g_psum[base + 1], s.y);
    atomicAdd(&g_psum[base + 2], s.z); atomicAdd(&g_psum[base + 3], s.w);
    atomicMaxF(&g_pmax[base + 0], m.x); atomicMaxF(&g_pmax[base + 1], m.y);
    atomicMaxF(&g_pmax[base + 2], m.z); atomicMaxF(&g_pmax[base + 3], m.w);
    if (lane == 0) atomicAdd(&g_pcnt[cur], cnt);
}

// ---------------- readout head ---------------------------------------------
__global__ void k_readout(const float* __restrict__ gfeat,
                          const float* __restrict__ Wg, const float* __restrict__ bg,
                          const float* __restrict__ Wo, const float* __restrict__ bo,
                          float* __restrict__ out) {
    __shared__ float flat[3 * FD];
    __shared__ float logits[2];
    int g = blockIdx.x, o = threadIdx.x;     // 128 threads
    float cnt = fmaxf((float)g_pcnt[g], 1.f);
    flat[o]       = g_psum[g * FD + o] / cnt;
    flat[FD + o]  = g_pmax[g * FD + o];
    float acc = bg[o];
#pragma unroll
    for (int k = 0; k < GF; k++) acc += gfeat[g * GF + k] * Wg[k * FD + o];
    flat[2 * FD + o] = acc;
    __syncthreads();
    if (o < 2) {
        float l = bo[o];
        for (int j = 0; j < 3 * FD; j++) l += flat[j] * Wo[j * 2 + o];
        logits[o] = l;
    }
    __syncthreads();
    if (o < 2) {
        float mm  = fmaxf(logits[0], logits[1]);
        float lse = mm + logf(expf(logits[0] - mm) + expf(logits[1] - mm));
        out[g * 2 + o] = logits[o] - lse;
    }
}

// ---------------- launch -----------------------------------------------------
extern "C" void kernel_launch(void* const* d_in, const int* in_sizes, int n_in,
                              void* d_out, int out_size) {
    const float* x     = (const float*)d_in[0];
    const int*   edges = (const int*)  d_in[1];
    const int*   batch = (const int*)  d_in[2];
    const float* gfeat = (const float*)d_in[3];
    const float* Wl0   = (const float*)d_in[4];
    const float* bl0   = (const float*)d_in[5];
    const float* Wr0   = (const float*)d_in[6];
    const float* Wl1   = (const float*)d_in[7];
    const float* bl1   = (const float*)d_in[8];
    const float* Wr1   = (const float*)d_in[9];
    const float* Wg    = (const float*)d_in[10];
    const float* bg    = (const float*)d_in[11];
    const float* Wo    = (const float*)d_in[12];
    const float* bo    = (const float*)d_in[13];
    float* out = (float*)d_out;

    cudaFuncSetAttribute(k_gemm, cudaFuncAttributeMaxDynamicSharedMemorySize,
                         GEMM_SMEM);

    __half *pU, *pB;
    float *p_h1;
    cudaGetSymbolAddress((void**)&pU, g_U);
    cudaGetSymbolAddress((void**)&pB, g_B);
    cudaGetSymbolAddress((void**)&p_h1, g_h1);

    const int scan_nb = (NN + SCAN_B - 1) / SCAN_B;   // 98
    const int gemm_nb = (NN + 127) / 128;             // 782

    k_init<<<(NN + 255) / 256, 256>>>();
    k_hist<<<(NE + 255) / 256, 256>>>(edges);
    k_scanA<<<scan_nb, SCAN_B>>>();
    k_scanB<<<1, 128>>>(scan_nb);
    k_scanC<<<scan_nb, SCAN_B>>>();
    k_fillcol<<<(NE + 255) / 256, 256>>>(edges);

    k_prepw<<<256, 256>>>(Wr0, Wl0, Wr1, Wl1);
    k_split_x<<<(NN * 32 + 255) / 256, 256>>>(x);

    // layer 0: gather fp16 x (U cols 0..127); GEMM writes h0 fp16 in place
    k_aggregate<<<(NN + 7) / 8, 256>>>();
    k_gemm<<<gemm_nb, 256, GEMM_SMEM>>>(pU, pB, bl0, nullptr, pU, 1, 1);
    // layer 1: gather fp16 h0; GEMM writes fp32 h1
    k_aggregate<<<(NN + 7) / 8, 256>>>();
    k_gemm<<<gemm_nb, 256, GEMM_SMEM>>>(pU, pB + 32768, bl1, p_h1, nullptr, 0, 0);

    // pooling + head
    int pool_warps  = (NN + 63) / 64;
    int pool_blocks = (pool_warps * 32 + 255) / 256;
    k_pool<<<pool_blocks, 256>>>(p_h1, batch);
    k_readout<<<NG, FD>>>(gfeat, Wg, bg, Wo, bo, out);
}

// round 11
// speedup vs baseline: 2.4412x; 1.1350x over previous
#include <cuda_runtime.h>
#include <cuda_fp16.h>
#include <cstdint>
#include <math.h>

#define NN 100000
#define NE 1600000
#define FD 128
#define NG 128
#define GF 32

#define B_SCALE 32.0f
#define B_INV   (1.0f / 32.0f)

// ---------------- scratch (device globals; no allocations allowed) ----------
__device__ __align__(16) unsigned char g_U[(size_t)NN * 256]; // [X|AGG] e4m3
__device__ __align__(16) unsigned char g_B[2 * 128 * 256];    // W^T e4m3 (x32)
__device__ __align__(16) float g_h1[(size_t)NN * FD];
__device__ int   g_deg[NN];
__device__ int   g_rowptr[NN + 1];
__device__ int   g_fill[NN];
__device__ int   g_col[NE];
__device__ float g_psum[NG * FD];
__device__ float g_pmax[NG * FD];
__device__ int   g_pcnt[NG];
__device__ int   g_bsum[128];

// ---------------- small helpers ---------------------------------------------
__device__ __forceinline__ void atomicMaxF(float* addr, float v) {
    if (v >= 0.f) atomicMax((int*)addr, __float_as_int(v));
    else          atomicMin((unsigned int*)addr, __float_as_uint(v));
}

// pack: byte0 = lo, byte1 = hi
__device__ __forceinline__ unsigned short f2e4m3x2(float hi, float lo) {
    unsigned short r;
    asm("cvt.rn.satfinite.e4m3x2.f32 %0, %1, %2;" : "=h"(r) : "f"(hi), "f"(lo));
    return r;
}
__device__ __forceinline__ float2 e4m3x2f2(unsigned short u) {
    uint32_t h2;
    asm("cvt.rn.f16x2.e4m3x2 %0, %1;" : "=r"(h2) : "h"(u));
    return __half22float2(*(__half2*)&h2);
}

__device__ __forceinline__ uint32_t smem_u32(const void* p) {
    uint32_t a;
    asm("{ .reg .u64 t; cvta.to.shared.u64 t, %1; cvt.u32.u64 %0, t; }"
        : "=r"(a) : "l"(p));
    return a;
}

__device__ __forceinline__ void ldsm4(uint32_t* r, uint32_t addr) {
    asm volatile("ldmatrix.sync.aligned.m8n8.x4.shared.b16 {%0,%1,%2,%3}, [%4];"
                 : "=r"(r[0]), "=r"(r[1]), "=r"(r[2]), "=r"(r[3]) : "r"(addr));
}
__device__ __forceinline__ void ldsm2(uint32_t* r, uint32_t addr) {
    asm volatile("ldmatrix.sync.aligned.m8n8.x2.shared.b16 {%0,%1}, [%2];"
                 : "=r"(r[0]), "=r"(r[1]) : "r"(addr));
}
__device__ __forceinline__ void mma_fp8(float* c, const uint32_t* a, const uint32_t* b) {
    asm volatile(
        "mma.sync.aligned.m16n8k32.row.col.f32.e4m3.e4m3.f32 "
        "{%0,%1,%2,%3}, {%4,%5,%6,%7}, {%8,%9}, {%0,%1,%2,%3};"
        : "+f"(c[0]), "+f"(c[1]), "+f"(c[2]), "+f"(c[3])
        : "r"(a[0]), "r"(a[1]), "r"(a[2]), "r"(a[3]), "r"(b[0]), "r"(b[1]));
}

// ---------------- CSR build -------------------------------------------------
__global__ void k_init() {
    int i = blockIdx.x * blockDim.x + threadIdx.x;
    if (i < NN) { g_deg[i] = 0; g_fill[i] = 0; }
    if (i < NG * FD) { g_psum[i] = 0.f; g_pmax[i] = -INFINITY; }
    if (i < NG) g_pcnt[i] = 0;
}

__global__ void k_hist(const int* __restrict__ edges) {
    int e = blockIdx.x * blockDim.x + threadIdx.x;
    if (e < NE) atomicAdd(&g_deg[edges[NE + e]], 1);
}

#define SCAN_B 1024
__global__ void k_scanA() {
    __shared__ int sm[SCAN_B];
    int i = blockIdx.x * SCAN_B + threadIdx.x;
    int v = (i < NN) ? g_deg[i] : 0;
    sm[threadIdx.x] = v;
    __syncthreads();
    for (int off = 1; off < SCAN_B; off <<= 1) {
        int t = (threadIdx.x >= off) ? sm[threadIdx.x - off] : 0;
        __syncthreads();
        sm[threadIdx.x] += t;
        __syncthreads();
    }
    if (i < NN) g_rowptr[i] = sm[threadIdx.x] - v;   // exclusive
    if (threadIdx.x == SCAN_B - 1) g_bsum[blockIdx.x] = sm[SCAN_B - 1];
}

__global__ void k_scanB(int nb) {                    // parallel Kogge-Stone
    __shared__ int s[128];
    int t = threadIdx.x;
    int v = (t < nb) ? g_bsum[t] : 0;
    s[t] = v;
    __syncthreads();
    for (int off = 1; off < 128; off <<= 1) {
        int u = (t >= off) ? s[t - off] : 0;
        __syncthreads();
        s[t] += u;
        __syncthreads();
    }
    if (t < nb) g_bsum[t] = s[t] - v;                // exclusive
}

__global__ void k_scanC() {
    int i = blockIdx.x * SCAN_B + threadIdx.x;
    if (i < NN) g_rowptr[i] += g_bsum[blockIdx.x];
    if (i == 0) g_rowptr[NN] = NE;
}

__global__ void k_fillcol(const int* __restrict__ edges) {
    int e = blockIdx.x * blockDim.x + threadIdx.x;
    if (e < NE) {
        int t = edges[NE + e];
        int p = g_rowptr[t] + atomicAdd(&g_fill[t], 1);
        g_col[p] = edges[e];
    }
}

// ---------------- weight prep: V = [Wr;Wl] -> B[n][k] e4m3 (x32) ------------
__global__ void k_prepw(const float* __restrict__ Wr0, const float* __restrict__ Wl0,
                        const float* __restrict__ Wr1, const float* __restrict__ Wl1) {
    int idx = blockIdx.x * 256 + threadIdx.x;        // 65536 total
    int L = idx >> 15;
    int rem = idx & 32767;
    int k = rem >> 7, n = rem & 127;
    const float* Wr = L ? Wr1 : Wr0;
    const float* Wl = L ? Wl1 : Wl0;
    float v = ((k < FD) ? Wr[k * FD + n] : Wl[(k - FD) * FD + n]) * B_SCALE;
    unsigned short p = f2e4m3x2(0.f, v);
    g_B[L * 32768 + n * 256 + k] = (unsigned char)(p & 0xFF);
}

// ---------------- split X into e4m3 (U cols 0..127) -------------------------
__global__ void k_split_x(const float* __restrict__ X) {
    int i = blockIdx.x * 256 + threadIdx.x;          // over NN*32 float4
    if (i >= NN * 32) return;
    float4 v = ((const float4*)X)[i];
    int node = i >> 5, q = (i & 31) * 4;             // byte offset
    uint32_t lo = f2e4m3x2(v.y, v.x);
    uint32_t hi = f2e4m3x2(v.w, v.z);
    *(uint32_t*)(g_U + (size_t)node * 256 + q) = lo | (hi << 16);
}

// ---------------- neighbor mean aggregation ----------------------------------
// Gathers e4m3 rows from g_U cols 0..127 (256B stride, 128B payload),
// accumulates fp32, writes e4m3 mean to U cols 128..255.
__global__ void k_aggregate() {
    int node = blockIdx.x * 8 + (threadIdx.x >> 5);
    int lane = threadIdx.x & 31;
    if (node >= NN) return;
    int beg = g_rowptr[node], end = g_rowptr[node + 1];
    const uint32_t* Hv = (const uint32_t*)g_U;       // 4 fp8 per lane
    float4 s = make_float4(0.f, 0.f, 0.f, 0.f);
    int e = beg;
    for (; e + 3 < end; e += 4) {
        int i0 = g_col[e], i1 = g_col[e + 1], i2 = g_col[e + 2], i3 = g_col[e + 3];
        uint32_t u0 = Hv[(size_t)i0 * 64 + lane];
        uint32_t u1 = Hv[(size_t)i1 * 64 + lane];
        uint32_t u2 = Hv[(size_t)i2 * 64 + lane];
        uint32_t u3 = Hv[(size_t)i3 * 64 + lane];
        float2 a0 = e4m3x2f2((unsigned short)u0), a1 = e4m3x2f2((unsigned short)(u0 >> 16));
        float2 b0 = e4m3x2f2((unsigned short)u1), b1 = e4m3x2f2((unsigned short)(u1 >> 16));
        float2 c0 = e4m3x2f2((unsigned short)u2), c1 = e4m3x2f2((unsigned short)(u2 >> 16));
        float2 d0 = e4m3x2f2((unsigned short)u3), d1 = e4m3x2f2((unsigned short)(u3 >> 16));
        s.x += (a0.x + b0.x) + (c0.x + d0.x);
        s.y += (a0.y + b0.y) + (c0.y + d0.y);
        s.z += (a1.x + b1.x) + (c1.x + d1.x);
        s.w += (a1.y + b1.y) + (c1.y + d1.y);
    }
    for (; e < end; e++) {
        uint32_t u = Hv[(size_t)g_col[e] * 64 + lane];
        float2 f0 = e4m3x2f2((unsigned short)u), f1 = e4m3x2f2((unsigned short)(u >> 16));
        s.x += f0.x; s.y += f0.y; s.z += f1.x; s.w += f1.y;
    }
    float sc = 1.f / fmaxf((float)(end - beg), 1.f);
    uint32_t lo = f2e4m3x2(s.y * sc, s.x * sc);
    uint32_t hi = f2e4m3x2(s.w * sc, s.z * sc);
    *(uint32_t*)(g_U + (size_t)node * 256 + 128 + lane * 4) = lo | (hi << 16);
}

// ---------------- mma.sync GEMM: e4m3 A x e4m3 B (m16n8k32) -----------------
// CTA: 128 nodes x 128 outs; 8 warps 2(M)x4(N); warp tile 64x32.
// K = 256 fp8 bytes, 2 chunks of 128B; ks step = 32 bytes (k32).
#define TPB 144
#define TILE_B (128 * TPB)                   // 18432 bytes per tile
#define GEMM_SMEM (2 * TILE_B + 512)

__device__ __forceinline__ void load_chunk(unsigned char* dst,
                                           const unsigned char* __restrict__ src,
                                           int row0, int rowmax, int kofs) {
    for (int i = threadIdx.x; i < 1024; i += 256) {  // uint4 units (16 fp8)
        int r = i >> 3, q = i & 7;
        int gr = row0 + r;
        uint4 v = make_uint4(0, 0, 0, 0);
        if (gr < rowmax) v = *(const uint4*)(src + (size_t)gr * 256 + kofs + q * 16);
        *(uint4*)(dst + r * TPB + q * 16) = v;
    }
}

__global__ __launch_bounds__(256, 2) void k_gemm(
    const unsigned char* __restrict__ U, const unsigned char* __restrict__ B,
    const float* __restrict__ bias, float* __restrict__ OUT,
    unsigned char* __restrict__ NU, int relu, int wsplit)
{
    extern __shared__ char smem[];
    unsigned char* sU = (unsigned char*)smem;
    unsigned char* sB = (unsigned char*)(smem + TILE_B);
    float* sbias = (float*)(smem + 2 * TILE_B);

    const int tid = threadIdx.x, wid = tid >> 5, lid = tid & 31;
    const int wm = wid >> 2, wn = wid & 3;
    const int node0 = blockIdx.x * 128;

    if (tid < FD) sbias[tid] = bias[tid];

    float acc[4][4][4];
#pragma unroll
    for (int mt = 0; mt < 4; mt++)
#pragma unroll
        for (int nt = 0; nt < 4; nt++)
#pragma unroll
            for (int j = 0; j < 4; j++) acc[mt][nt][j] = 0.f;

    uint32_t aU = smem_u32(sU), aB = smem_u32(sB);
    const uint32_t a_lane = (uint32_t)((lid & 15) * TPB + ((lid >> 4) << 4));
    const uint32_t b_lane = (uint32_t)((lid & 7) * TPB + (((lid >> 3) & 1) << 4));

    for (int c = 0; c < 2; c++) {
        load_chunk(sU, U, node0, NN, c * 128);
        load_chunk(sB, B, 0, 128, c * 128);
        __syncthreads();
#pragma unroll
        for (int ks = 0; ks < 4; ks++) {
            uint32_t ah[4][4];
#pragma unroll
            for (int mt = 0; mt < 4; mt++) {
                uint32_t roff = (uint32_t)((wm * 64 + mt * 16) * TPB + ks * 32);
                ldsm4(ah[mt], aU + roff + a_lane);
            }
#pragma unroll
            for (int nt = 0; nt < 4; nt++) {
                uint32_t bb[2];
                uint32_t roff = (uint32_t)((wn * 32 + nt * 8) * TPB + ks * 32);
                ldsm2(bb, aB + roff + b_lane);
#pragma unroll
                for (int mt = 0; mt < 4; mt++)
                    mma_fp8(acc[mt][nt], ah[mt], bb);
            }
        }
        __syncthreads();
    }

    // epilogue: c-fragment (row = t/4 [+8], col = 2*(t%4) [+1])
    const int tq = lid >> 2, tr = lid & 3;
#pragma unroll
    for (int mt = 0; mt < 4; mt++) {
#pragma unroll
        for (int h = 0; h < 2; h++) {
            int node = node0 + wm * 64 + mt * 16 + tq + h * 8;
            if (node >= NN) continue;
#pragma unroll
            for (int nt = 0; nt < 4; nt++) {
                int col = wn * 32 + nt * 8 + tr * 2;
                float v0 = acc[mt][nt][h * 2 + 0] * B_INV + sbias[col];
                float v1 = acc[mt][nt][h * 2 + 1] * B_INV + sbias[col + 1];
                if (relu) { v0 = fmaxf(v0, 0.f); v1 = fmaxf(v1, 0.f); }
                if (wsplit) {
                    // layer 0: store h0 as e4m3 into U cols 0..127
                    *(unsigned short*)(NU + (size_t)node * 256 + col) =
                        f2e4m3x2(v1, v0);
                } else {
                    *(float2*)(OUT + (size_t)node * FD + col) = make_float2(v0, v1);
                }
            }
        }
    }
}

// ---------------- pooling (sorted batch_idx, warp-local segments) -----------
__global__ void k_pool(const float* __restrict__ H, const int* __restrict__ batch) {
    int wg   = (blockIdx.x * blockDim.x + threadIdx.x) >> 5;
    int lane = threadIdx.x & 31;
    int n0 = wg * 64;
    if (n0 >= NN) return;
    int n1 = min(n0 + 64, NN);
    const float4* Hv = (const float4*)H;
    float4 s = make_float4(0.f, 0.f, 0.f, 0.f);
    float4 m = make_float4(-INFINITY, -INFINITY, -INFINITY, -INFINITY);
    int cnt = 0, cur = batch[n0];
    for (int n = n0; n < n1; n++) {
        int g = batch[n];
        if (g != cur) {
            int base = cur * FD + lane * 4;
            atomicAdd(&g_psum[base + 0], s.x); atomicAdd(&g_psum[base + 1], s.y);
            atomicAdd(&g_psum[base + 2], s.z); atomicAdd(&g_psum[base + 3], s.w);
            atomicMaxF(&g_pmax[base + 0], m.x); atomicMaxF(&g_pmax[base + 1], m.y);
            atomicMaxF(&g_pmax[base + 2], m.z); atomicMaxF(&g_pmax[base + 3], m.w);
            if (lane == 0) atomicAdd(&g_pcnt[cur], cnt);
            s = make_float4(0.f, 0.f, 0.f, 0.f);
            m = make_float4(-INFINITY, -INFINITY, -INFINITY, -INFINITY);
            cnt = 0; cur = g;
        }
        float4 v = Hv[(size_t)n * 32 + lane];
        s.x += v.x; s.y += v.y; s.z += v.z; s.w += v.w;
        m.x = fmaxf(m.x, v.x); m.y = fmaxf(m.y, v.y);
        m.z = fmaxf(m.z, v.z); m.w = fmaxf(m.w, v.w);
        cnt++;
    }
    int base = cur * FD + lane * 4;
    atomicAdd(&g_psum[base + 0], s.x); atomicAdd(&g_psum[base + 1], s.y);
    atomicAdd(&g_psum[base + 2], s.z); atomicAdd(&g_psum[base + 3], s.w);
    atomicMaxF(&g_pmax[base + 0], m.x); atomicMaxF(&g_pmax[base + 1], m.y);
    atomicMaxF(&g_pmax[base + 2], m.z); atomicMaxF(&g_pmax[base + 3], m.w);
    if (lane == 0) atomicAdd(&g_pcnt[cur], cnt);
}

// ---------------- readout head ---------------------------------------------
__global__ void k_readout(const float* __restrict__ gfeat,
                          const float* __restrict__ Wg, const float* __restrict__ bg,
                          const float* __restrict__ Wo, const float* __restrict__ bo,
                          float* __restrict__ out) {
    __shared__ float flat[3 * FD];
    __shared__ float logits[2];
    int g = blockIdx.x, o = threadIdx.x;     // 128 threads
    float cnt = fmaxf((float)g_pcnt[g], 1.f);
    flat[o]       = g_psum[g * FD + o] / cnt;
    flat[FD + o]  = g_pmax[g * FD + o];
    float acc = bg[o];
#pragma unroll
    for (int k = 0; k < GF; k++) acc += gfeat[g * GF + k] * Wg[k * FD + o];
    flat[2 * FD + o] = acc;
    __syncthreads();
    if (o < 2) {
        float l = bo[o];
        for (int j = 0; j < 3 * FD; j++) l += flat[j] * Wo[j * 2 + o];
        logits[o] = l;
    }
    __syncthreads();
    if (o < 2) {
        float mm  = fmaxf(logits[0], logits[1]);
        float lse = mm + logf(expf(logits[0] - mm) + expf(logits[1] - mm));
        out[g * 2 + o] = logits[o] - lse;
    }
}

// ---------------- launch -----------------------------------------------------
extern "C" void kernel_launch(void* const* d_in, const int* in_sizes, int n_in,
                              void* d_out, int out_size) {
    const float* x     = (const float*)d_in[0];
    const int*   edges = (const int*)  d_in[1];
    const int*   batch = (const int*)  d_in[2];
    const float* gfeat = (const float*)d_in[3];
    const float* Wl0   = (const float*)d_in[4];
    const float* bl0   = (const float*)d_in[5];
    const float* Wr0   = (const float*)d_in[6];
    const float* Wl1   = (const float*)d_in[7];
    const float* bl1   = (const float*)d_in[8];
    const float* Wr1   = (const float*)d_in[9];
    const float* Wg    = (const float*)d_in[10];
    const float* bg    = (const float*)d_in[11];
    const float* Wo    = (const float*)d_in[12];
    const float* bo    = (const float*)d_in[13];
    float* out = (float*)d_out;

    cudaFuncSetAttribute(k_gemm, cudaFuncAttributeMaxDynamicSharedMemorySize,
                         GEMM_SMEM);

    unsigned char *pU, *pB;
    float *p_h1;
    cudaGetSymbolAddress((void**)&pU, g_U);
    cudaGetSymbolAddress((void**)&pB, g_B);
    cudaGetSymbolAddress((void**)&p_h1, g_h1);

    const int scan_nb = (NN + SCAN_B - 1) / SCAN_B;   // 98
    const int gemm_nb = (NN + 127) / 128;             // 782

    k_init<<<(NN + 255) / 256, 256>>>();
    k_hist<<<(NE + 255) / 256, 256>>>(edges);
    k_scanA<<<scan_nb, SCAN_B>>>();
    k_scanB<<<1, 128>>>(scan_nb);
    k_scanC<<<scan_nb, SCAN_B>>>();
    k_fillcol<<<(NE + 255) / 256, 256>>>(edges);

    k_prepw<<<256, 256>>>(Wr0, Wl0, Wr1, Wl1);
    k_split_x<<<(NN * 32 + 255) / 256, 256>>>(x);

    // layer 0: gather e4m3 x (U cols 0..127); GEMM writes h0 e4m3 in place
    k_aggregate<<<(NN + 7) / 8, 256>>>();
    k_gemm<<<gemm_nb, 256, GEMM_SMEM>>>(pU, pB, bl0, nullptr, pU, 1, 1);
    // layer 1: gather e4m3 h0; GEMM writes fp32 h1
    k_aggregate<<<(NN + 7) / 8, 256>>>();
    k_gemm<<<gemm_nb, 256, GEMM_SMEM>>>(pU, pB + 32768, bl1, p_h1, nullptr, 0, 0);

    // pooling + head
    int pool_warps  = (NN + 63) / 64;
    int pool_blocks = (pool_warps * 32 + 255) / 256;
    k_pool<<<pool_blocks, 256>>>(p_h1, batch);
    k_readout<<<NG, FD>>>(gfeat, Wg, bg, Wo, bo, out);
}